// round 13
// baseline (speedup 1.0000x reference)
#include <cuda_runtime.h>
#include <cuda_fp16.h>
#include <math.h>
#include <stdint.h>

// Problem constants
#define BB   2
#define SS   256
#define INP  80
#define HID  128
#define F2   256
#define G4   512   // 4*HID
#define NCC  40
#define WSEG 64

typedef unsigned long long u64;

// ---------------- device scratch (no allocation allowed) ----------------
__device__ float g_WihT0[2][INP][G4];    // [dir][i][g]
__device__ float g_WihT1[2][F2][G4];
__device__ float g_pre[2][BB][SS][G4];   // [dir][b][s][g]  (reused per layer)
__device__ float g_rnn[2][BB][SS][F2];   // [layer][b][s][f]
__device__ float g_cum[BB][SS][F2];
__device__ float g_WcT[F2][128];         // w_s1 c-part transposed, o padded 100->128 (zeros)
__device__ float g_WdT[F2][128];
__device__ float g_WeT[F2][128];
__device__ float g_wc1T[F2][80];
__device__ float g_wb1T[F2][80];
__device__ float g_dterm[BB][SS][128];   // prelu(rnn_i)@Wd^T + b_s1 (padded)
__device__ float g_eterm[BB][SS][128];   // prelu(rnn_j)@We^T
__device__ float g_scoresT[BB][SS][SS];  // scoresT[b][j][i] = scores[i][j] (DP reads rows)

__device__ __forceinline__ float preluf(float x, float a) { return x >= 0.0f ? x : a * x; }
// single-MUFU activations (tanh.approx.f32)
__device__ __forceinline__ float tanh_ap(float x) {
    float y; asm("tanh.approx.f32 %0, %1;" : "=f"(y) : "f"(x)); return y;
}
__device__ __forceinline__ float sig_ap(float x) { return fmaf(tanh_ap(0.5f * x), 0.5f, 0.5f); }

// ---------------- f32x2 packed math helpers ----------------
__device__ __forceinline__ void fma2(u64& acc, u64 a, u64 b) {
    asm("fma.rn.f32x2 %0, %1, %2, %0;" : "+l"(acc) : "l"(a), "l"(b));
}
__device__ __forceinline__ u64 packf2(float lo, float hi) {
    u64 r; asm("mov.b64 %0, {%1, %2};" : "=l"(r) : "f"(lo), "f"(hi)); return r;
}
__device__ __forceinline__ float2 unpackf2(u64 v) {
    float2 r; asm("mov.b64 {%0, %1}, %2;" : "=f"(r.x), "=f"(r.y) : "l"(v)); return r;
}

// ---------------- prep: transpose weights into friendly layouts ----------------
__global__ void prep_k(const float* __restrict__ wih0f,
                       const float* __restrict__ wih0b,
                       const float* __restrict__ wih1f,
                       const float* __restrict__ wih1b,
                       const float* __restrict__ ws1,  const float* __restrict__ wc1,
                       const float* __restrict__ wb1)
{
    int idx = blockIdx.x * blockDim.x + threadIdx.x;
    int n = gridDim.x * blockDim.x;
    for (int p = idx; p < 2 * INP * G4; p += n) {
        int d = p / (INP * G4), r = p % (INP * G4), i = r / G4, g = r % G4;
        g_WihT0[d][i][g] = (d ? wih0b : wih0f)[g * INP + i];
    }
    for (int p = idx; p < 2 * F2 * G4; p += n) {
        int d = p / (F2 * G4), r = p % (F2 * G4), i = r / G4, g = r % G4;
        g_WihT1[d][i][g] = (d ? wih1b : wih1f)[g * F2 + i];
    }
    for (int p = idx; p < F2 * 128; p += n) {
        int k = p / 128, o = p % 128;
        g_WcT[k][o] = (o < 100) ? ws1[o * 768 + k]        : 0.0f;
        g_WdT[k][o] = (o < 100) ? ws1[o * 768 + 256 + k]  : 0.0f;
        g_WeT[k][o] = (o < 100) ? ws1[o * 768 + 512 + k]  : 0.0f;
    }
    for (int p = idx; p < F2 * 80; p += n) {
        int k = p / 80, o = p % 80;
        g_wc1T[k][o] = wc1[o * F2 + k];
        g_wb1T[k][o] = wb1[o * F2 + k];
    }
}

// ---------------- input projection: pre = x @ Wih^T + b ----------------
template <int INDIM>
__global__ void inproj_k(const float* __restrict__ x0,
                         const float* __restrict__ bias_f, const float* __restrict__ bias_b,
                         int layer)
{
    int st = blockIdx.x * 4, b = blockIdx.y, d = blockIdx.z, g = threadIdx.x;
    __shared__ float xs[4][INDIM];
    const float* xin = layer ? &g_rnn[0][0][0][0] : x0;
    for (int p = g; p < 4 * INDIM; p += 512) {
        int ss = p / INDIM, i = p % INDIM;
        xs[ss][i] = xin[(b * SS + st + ss) * INDIM + i];
    }
    __syncthreads();
    const float* W = (INDIM == INP) ? &g_WihT0[d][0][0] : &g_WihT1[d][0][0];
    float bg = (d ? bias_b : bias_f)[g];
    float acc[4] = {bg, bg, bg, bg};
    for (int i = 0; i < INDIM; i += 8) {
        float w[8];
#pragma unroll
        for (int q = 0; q < 8; q++) w[q] = W[(i + q) * G4 + g];
#pragma unroll
        for (int ss = 0; ss < 4; ss++) {
            float a = acc[ss];
#pragma unroll
            for (int q = 0; q < 8; q++) a = fmaf(xs[ss][i + q], w[q], a);
            acc[ss] = a;
        }
    }
#pragma unroll
    for (int ss = 0; ss < 4; ss++) g_pre[d][b][st + ss][g] = acc[ss];
}

// ---------------- LSTM recurrence: ONE CTA per chain, fp16 weights in registers ------
// 512 threads, thread t = gate row t (gate = t>>7, unit = t&127). Full 128-k weight
// row lives in 64 half2 registers (fp16 storage, fp32 accumulate). No cluster, no
// DSMEM, no mbarriers. Per step: matvec -> STS gate -> __syncthreads -> EVERY warp
// redundantly computes the full 128-unit cell (c replicated per warp, deterministic,
// 4 units/lane) and writes all 128 h values itself -> __syncwarp -> next matvec.
// Only ONE block-wide sync per step; h double-buffered so a fast warp's next-step
// reads never conflict with a slow warp's current-step reads (redundant writers
// store identical bits - benign).
__global__ void __launch_bounds__(512, 1)
recur_k(const float* __restrict__ whh_f, const float* __restrict__ whh_b, int layer)
{
    __shared__ alignas(16) float hbuf[2][HID];
    __shared__ float gloc[G4];
    int t = threadIdx.x;
    int chain = blockIdx.x;
    int b = chain >> 1, d = chain & 1;
    const float* __restrict__ whh = d ? whh_b : whh_f;

    // full 128-weight row as 64 half2 regs (fp16 storage; ~4.9e-4 relative rounding)
    __half2 wreg[64];
    {
        const float2* wrow = reinterpret_cast<const float2*>(whh + t * 128);
#pragma unroll
        for (int q = 0; q < 64; q++) wreg[q] = __float22half2_rn(wrow[q]);
    }

    if (t < HID) hbuf[0][t] = 0.0f;
    __syncthreads();

    const float* __restrict__ preB = &g_pre[d][b][0][0];
    float* __restrict__ outB = &g_rnn[layer][b][0][0];
    int lane = t & 31;
    int warp0 = (t < 32);
    float c[4] = {0.0f, 0.0f, 0.0f, 0.0f};   // cell state, replicated per warp

    int s0 = d ? (SS - 1) : 0;
    float pre = __ldg(&preB[s0 * G4 + t]);

    for (int step = 0; step < SS; ++step) {
        int buf = step & 1, bn = buf ^ 1;
        int s = d ? (SS - 1 - step) : step;

        // matvec: fp16 weights -> fp32, h from smem, fp32 accumulate
        float a0 = pre, a1 = 0.0f, a2 = 0.0f, a3 = 0.0f;
        const float4* hp = reinterpret_cast<const float4*>(&hbuf[buf][0]);
#pragma unroll
        for (int g4 = 0; g4 < 32; g4++) {
            float4 h = hp[g4];
            float2 wa = __half22float2(wreg[2 * g4]);
            float2 wb = __half22float2(wreg[2 * g4 + 1]);
            a0 = fmaf(h.x, wa.x, a0);
            a1 = fmaf(h.y, wa.y, a1);
            a2 = fmaf(h.z, wb.x, a2);
            a3 = fmaf(h.w, wb.y, a3);
        }
        gloc[t] = (a0 + a1) + (a2 + a3);

        // prefetch next pre (independent of h chain)
        if (step + 1 < SS) {
            int sn = d ? (SS - 2 - step) : (step + 1);
            pre = __ldg(&preB[sn * G4 + t]);
        }
        __syncthreads();   // gloc ready (the only block sync per step)

        // redundant cell: every warp computes all 128 units (4 per lane)
#pragma unroll
        for (int q = 0; q < 4; q++) {
            int u = lane + 32 * q;
            float gi = gloc[u], gf = gloc[HID + u], gg = gloc[2 * HID + u], go = gloc[3 * HID + u];
            c[q] = sig_ap(gf) * c[q] + sig_ap(gi) * tanh_ap(gg);
            float h = sig_ap(go) * tanh_ap(c[q]);
            hbuf[bn][u] = h;                 // all warps write identical values
            if (warp0) outB[s * F2 + d * HID + u] = h;
        }
        __syncwarp();   // this warp's own hbuf[bn] writes visible to itself
    }
}

// ---------------- cumsum over time ----------------
__global__ void cumsum_k()
{
    int b = blockIdx.x, k = threadIdx.x; // 256
    float run = 0.0f;
#pragma unroll 4
    for (int s = 0; s < SS; s++) {
        run += g_rnn[1][b][s][k];
        g_cum[b][s][k] = run;
    }
}

// ---------------- dterm/eterm precompute ----------------
__global__ void determ_k(const float* __restrict__ a_s0p, const float* __restrict__ bs1)
{
    int s = blockIdx.x, b = blockIdx.y, t = threadIdx.x; // 128
    __shared__ float pr[F2];
    float a0 = *a_s0p;
    for (int p = t; p < F2; p += 128) pr[p] = preluf(g_rnn[1][b][s][p], a0);
    __syncthreads();
    float ad = 0.0f, ae = 0.0f;
    for (int k = 0; k < F2; k++) {
        float p = pr[k];
        ad = fmaf(p, g_WdT[k][t], ad);
        ae = fmaf(p, g_WeT[k][t], ae);
    }
    g_dterm[b][s][t] = ad + ((t < 100) ? bs1[t] : 0.0f);
    g_eterm[b][s][t] = ae;
}

// ---------------- cls / bin MLPs ----------------
__global__ void clsbin_k(const float* __restrict__ ac0, const float* __restrict__ bc1,
                         const float* __restrict__ ac1, const float* __restrict__ wc2,
                         const float* __restrict__ bc2,
                         const float* __restrict__ ab0, const float* __restrict__ bb1,
                         const float* __restrict__ ab1, const float* __restrict__ wb2,
                         const float* __restrict__ bb2, float* __restrict__ out)
{
    int s = blockIdx.x, b = blockIdx.y, t = threadIdx.x; // 128
    __shared__ float pr[F2];
    __shared__ float h1[80];
    float a = *ac0;
    for (int p = t; p < F2; p += 128) pr[p] = preluf(g_rnn[1][b][s][p], a);
    __syncthreads();
    if (t < 80) {
        float acc = bc1[t];
        for (int k = 0; k < F2; k++) acc = fmaf(pr[k], g_wc1T[k][t], acc);
        h1[t] = preluf(acc, *ac1);
    }
    __syncthreads();
    if (t < NCC) {
        float acc = bc2[t];
        for (int q = 0; q < 80; q++) acc = fmaf(h1[q], wc2[t * 80 + q], acc);
        out[(b * SS + s) * NCC + t] = acc;
    }
    __syncthreads();
    a = *ab0;
    for (int p = t; p < F2; p += 128) pr[p] = preluf(g_rnn[1][b][s][p], a);
    __syncthreads();
    if (t < 80) {
        float acc = bb1[t];
        for (int k = 0; k < F2; k++) acc = fmaf(pr[k], g_wb1T[k][t], acc);
        h1[t] = preluf(acc, *ab1);
    }
    __syncthreads();
    if (t < 2) {
        float acc = bb2[t];
        for (int q = 0; q < 80; q++) acc = fmaf(h1[q], wb2[t * 80 + q], acc);
        out[20480 + (b * SS + s) * 2 + t] = acc;
    }
}

// ---------------- pairwise scores: f32x2 packed, block=(i,b), 256 threads ----------------
#define T2ROW 130
__global__ void __launch_bounds__(256) scores_k(const float* __restrict__ a_s0p,
                         const float* __restrict__ a_s1p,
                         const float* __restrict__ ws2, const float* __restrict__ bs2)
{
    extern __shared__ float smd[];
    float* cum_i = smd;                                  // 256 floats
    u64* T2 = reinterpret_cast<u64*>(smd + 256);         // [64][T2ROW]
    int i = blockIdx.x, b = blockIdx.y, tid = threadIdx.x;
    int oq = tid & 15, jg = tid >> 4;   // 16 output-groups x 16 j-groups (4 j each)
    float a0 = *a_s0p, a1 = *a_s1p;
    for (int p = tid; p < F2; p += 256) cum_i[p] = g_cum[b][i][p];
    float dt[8], w2v[8];
#pragma unroll
    for (int r = 0; r < 8; r++) {
        int o = oq * 8 + r;
        dt[r] = g_dterm[b][i][o];
        w2v[r] = (o < 100) ? ws2[o] : 0.0f;
    }
    float bs2v = bs2[0];
    __syncthreads();
    const ulonglong2* __restrict__ W2 = reinterpret_cast<const ulonglong2*>(&g_WcT[0][0]);
    for (int tile = 0; tile < 4; tile++) {
        int j0 = tile * 64;
        u64 acc[4][4];
#pragma unroll
        for (int r4 = 0; r4 < 4; r4++)
#pragma unroll
            for (int p2 = 0; p2 < 4; p2++) acc[r4][p2] = 0ull;

        for (int kh = 0; kh < 2; kh++) {
            int kb = kh * 128;
            for (int p = tid; p < 64 * 128; p += 256) {
                int lj = p >> 7, k = p & 127;
                float v = preluf(g_cum[b][j0 + lj][kb + k] - cum_i[kb + k], a0);
                T2[lj * T2ROW + k] = packf2(v, v);
            }
            __syncthreads();
            const u64* Ta = &T2[(jg * 4 + 0) * T2ROW];
            const u64* Tb = &T2[(jg * 4 + 1) * T2ROW];
            const u64* Tc = &T2[(jg * 4 + 2) * T2ROW];
            const u64* Td = &T2[(jg * 4 + 3) * T2ROW];
#pragma unroll 2
            for (int k = 0; k < 128; k++) {
                ulonglong2 wA = W2[(kb + k) * 32 + 2 * oq];
                ulonglong2 wB = W2[(kb + k) * 32 + 2 * oq + 1];
                u64 t0 = Ta[k], t1 = Tb[k], t2 = Tc[k], t3 = Td[k];
                fma2(acc[0][0], t0, wA.x); fma2(acc[0][1], t0, wA.y);
                fma2(acc[0][2], t0, wB.x); fma2(acc[0][3], t0, wB.y);
                fma2(acc[1][0], t1, wA.x); fma2(acc[1][1], t1, wA.y);
                fma2(acc[1][2], t1, wB.x); fma2(acc[1][3], t1, wB.y);
                fma2(acc[2][0], t2, wA.x); fma2(acc[2][1], t2, wA.y);
                fma2(acc[2][2], t2, wB.x); fma2(acc[2][3], t2, wB.y);
                fma2(acc[3][0], t3, wA.x); fma2(acc[3][1], t3, wA.y);
                fma2(acc[3][2], t3, wB.x); fma2(acc[3][3], t3, wB.y);
            }
            __syncthreads();
        }
#pragma unroll
        for (int r4 = 0; r4 < 4; r4++) {
            int j = j0 + jg * 4 + r4;
            float part = 0.0f;
#pragma unroll
            for (int p2 = 0; p2 < 4; p2++) {
                float2 f = unpackf2(acc[r4][p2]);
                int r = 2 * p2, o = oq * 8 + r;
                float h0 = f.x + dt[r]     + g_eterm[b][j][o];
                float h1 = f.y + dt[r + 1] + g_eterm[b][j][o + 1];
                part = fmaf(preluf(h0, a1), w2v[r],     part);
                part = fmaf(preluf(h1, a1), w2v[r + 1], part);
            }
#pragma unroll
            for (int off = 8; off > 0; off >>= 1)
                part += __shfl_down_sync(0xffffffffu, part, off, 16);
            if (oq == 0) g_scoresT[b][j][i] = part + bs2v;
        }
    }
}

// ---------------- DP backpointers + fused backtrack ----------------
__global__ void dp_k(const int* __restrict__ lengths, float* __restrict__ out)
{
    int b = blockIdx.x, t = threadIdx.x; // 64 threads
    __shared__ float best[SS];
    __shared__ int bptr[SS];
    __shared__ float rv[2];
    __shared__ int ri[2];
    for (int p = t; p < SS; p += 64) { best[p] = 0.0f; out[21504 + b * SS + p] = 0.0f; }
    if (t == 0) bptr[0] = 0;
    __syncthreads();
    float sc_next = g_scoresT[b][1][t];   // i=1: start=0
    for (int i = 1; i < SS; i++) {
        int start = (i > WSEG) ? (i - WSEG) : 0;
        float sc = sc_next;
        if (i + 1 < SS) {
            int st2 = (i + 1 > WSEG) ? (i + 1 - WSEG) : 0;
            sc_next = g_scoresT[b][i + 1][st2 + t];
        }
        int j = start + t;
        float v = (j < i) ? best[j] + sc : -1000000000.0f;
        int idx = j;
#pragma unroll
        for (int off = 16; off > 0; off >>= 1) {
            float ov = __shfl_down_sync(0xffffffffu, v, off);
            int oi = __shfl_down_sync(0xffffffffu, idx, off);
            if (ov > v || (ov == v && oi < idx)) { v = ov; idx = oi; }
        }
        if ((t & 31) == 0) { rv[t >> 5] = v; ri[t >> 5] = idx; }
        __syncthreads();
        if (t == 0) {
            float v0 = rv[0], v1 = rv[1];
            int i0 = ri[0], i1 = ri[1];
            if (v1 > v0 || (v1 == v0 && i1 < i0)) { v0 = v1; i0 = i1; }
            best[i] = v0;
            bptr[i] = i0;
        }
        __syncthreads();
    }
    // fused backtrack: pred_scores = best[len-1]; bmask via smem pointer chase
    if (t == 0) {
        int cur = lengths[b] - 1;
        out[22016 + b] = (cur > 0) ? best[cur] : 0.0f;
        for (int it = 0; it < SS; it++) {
            out[21504 + b * SS + cur] = 1.0f;
            if (cur > 0) cur = bptr[cur];
        }
    }
}

// ---------------- launch ----------------
extern "C" void kernel_launch(void* const* d_in, const int* in_sizes, int n_in,
                              void* d_out, int out_size)
{
    const float* x       = (const float*)d_in[0];
    const int*   lengths = (const int*)d_in[1];
    const float* wih0f = (const float*)d_in[2];
    const float* whh0f = (const float*)d_in[3];
    const float* bl0f  = (const float*)d_in[4];
    const float* wih0b = (const float*)d_in[5];
    const float* whh0b = (const float*)d_in[6];
    const float* bl0b  = (const float*)d_in[7];
    const float* wih1f = (const float*)d_in[8];
    const float* whh1f = (const float*)d_in[9];
    const float* bl1f  = (const float*)d_in[10];
    const float* wih1b = (const float*)d_in[11];
    const float* whh1b = (const float*)d_in[12];
    const float* bl1b  = (const float*)d_in[13];
    const float* a_s0 = (const float*)d_in[14];
    const float* w_s1 = (const float*)d_in[15];
    const float* b_s1 = (const float*)d_in[16];
    const float* a_s1 = (const float*)d_in[17];
    const float* w_s2 = (const float*)d_in[18];
    const float* b_s2 = (const float*)d_in[19];
    const float* a_c0 = (const float*)d_in[20];
    const float* w_c1 = (const float*)d_in[21];
    const float* b_c1 = (const float*)d_in[22];
    const float* a_c1 = (const float*)d_in[23];
    const float* w_c2 = (const float*)d_in[24];
    const float* b_c2 = (const float*)d_in[25];
    const float* a_b0 = (const float*)d_in[26];
    const float* w_b1 = (const float*)d_in[27];
    const float* b_b1 = (const float*)d_in[28];
    const float* a_b1 = (const float*)d_in[29];
    const float* w_b2 = (const float*)d_in[30];
    const float* b_b2 = (const float*)d_in[31];
    float* out = (float*)d_out;

    const int SCORES_SMEM = 256 * 4 + 64 * T2ROW * 8;   // ~67.6 KB
    cudaFuncSetAttribute(scores_k, cudaFuncAttributeMaxDynamicSharedMemorySize, SCORES_SMEM);

    prep_k<<<512, 256>>>(wih0f, wih0b, wih1f, wih1b, w_s1, w_c1, w_b1);

    inproj_k<INP><<<dim3(SS / 4, BB, 2), 512>>>(x, bl0f, bl0b, 0);
    recur_k<<<4, 512>>>(whh0f, whh0b, 0);
    inproj_k<F2><<<dim3(SS / 4, BB, 2), 512>>>(x, bl1f, bl1b, 1);
    recur_k<<<4, 512>>>(whh1f, whh1b, 1);

    cumsum_k<<<BB, F2>>>();
    determ_k<<<dim3(SS, BB), 128>>>(a_s0, b_s1);
    clsbin_k<<<dim3(SS, BB), 128>>>(a_c0, b_c1, a_c1, w_c2, b_c2,
                                    a_b0, b_b1, a_b1, w_b2, b_b2, out);
    scores_k<<<dim3(SS, BB), 256, SCORES_SMEM>>>(a_s0, a_s1, w_s2, b_s2);
    dp_k<<<BB, 64>>>(lengths, out);
}

// round 14
// speedup vs baseline: 1.7136x; 1.7136x over previous
#include <cuda_runtime.h>
#include <cuda_fp16.h>
#include <math.h>
#include <stdint.h>

// Problem constants
#define BB   2
#define SS   256
#define INP  80
#define HID  128
#define F2   256
#define G4   512   // 4*HID
#define NCC  40
#define WSEG 64

typedef unsigned long long u64;

// ---------------- device scratch (no allocation allowed) ----------------
__device__ float g_WihT0[2][INP][G4];    // [dir][i][g]
__device__ float g_WihT1[2][F2][G4];
__device__ float g_pre[2][BB][SS][G4];   // [dir][b][s][g]  (reused per layer)
__device__ float g_rnn[2][BB][SS][F2];   // [layer][b][s][f]
__device__ float g_cum[BB][SS][F2];
__device__ float g_WcT[F2][128];         // w_s1 c-part transposed, o padded 100->128 (zeros)
__device__ float g_WdT[F2][128];
__device__ float g_WeT[F2][128];
__device__ float g_wc1T[F2][80];
__device__ float g_wb1T[F2][80];
__device__ float g_dterm[BB][SS][128];   // prelu(rnn_i)@Wd^T + b_s1 (padded)
__device__ float g_eterm[BB][SS][128];   // prelu(rnn_j)@We^T
__device__ float g_scoresT[BB][SS][SS];  // scoresT[b][j][i] = scores[i][j] (DP reads rows)

__device__ __forceinline__ float preluf(float x, float a) { return x >= 0.0f ? x : a * x; }
// single-MUFU activations (tanh.approx.f32)
__device__ __forceinline__ float tanh_ap(float x) {
    float y; asm("tanh.approx.f32 %0, %1;" : "=f"(y) : "f"(x)); return y;
}
__device__ __forceinline__ float sig_ap(float x) { return fmaf(tanh_ap(0.5f * x), 0.5f, 0.5f); }

// ---------------- f32x2 packed math helpers ----------------
__device__ __forceinline__ void fma2(u64& acc, u64 a, u64 b) {
    asm("fma.rn.f32x2 %0, %1, %2, %0;" : "+l"(acc) : "l"(a), "l"(b));
}
__device__ __forceinline__ u64 packf2(float lo, float hi) {
    u64 r; asm("mov.b64 %0, {%1, %2};" : "=l"(r) : "f"(lo), "f"(hi)); return r;
}
__device__ __forceinline__ float2 unpackf2(u64 v) {
    float2 r; asm("mov.b64 {%0, %1}, %2;" : "=f"(r.x), "=f"(r.y) : "l"(v)); return r;
}

// ---------------- prep: transpose weights into friendly layouts ----------------
__global__ void prep_k(const float* __restrict__ wih0f,
                       const float* __restrict__ wih0b,
                       const float* __restrict__ wih1f,
                       const float* __restrict__ wih1b,
                       const float* __restrict__ ws1,  const float* __restrict__ wc1,
                       const float* __restrict__ wb1)
{
    int idx = blockIdx.x * blockDim.x + threadIdx.x;
    int n = gridDim.x * blockDim.x;
    for (int p = idx; p < 2 * INP * G4; p += n) {
        int d = p / (INP * G4), r = p % (INP * G4), i = r / G4, g = r % G4;
        g_WihT0[d][i][g] = (d ? wih0b : wih0f)[g * INP + i];
    }
    for (int p = idx; p < 2 * F2 * G4; p += n) {
        int d = p / (F2 * G4), r = p % (F2 * G4), i = r / G4, g = r % G4;
        g_WihT1[d][i][g] = (d ? wih1b : wih1f)[g * F2 + i];
    }
    for (int p = idx; p < F2 * 128; p += n) {
        int k = p / 128, o = p % 128;
        g_WcT[k][o] = (o < 100) ? ws1[o * 768 + k]        : 0.0f;
        g_WdT[k][o] = (o < 100) ? ws1[o * 768 + 256 + k]  : 0.0f;
        g_WeT[k][o] = (o < 100) ? ws1[o * 768 + 512 + k]  : 0.0f;
    }
    for (int p = idx; p < F2 * 80; p += n) {
        int k = p / 80, o = p % 80;
        g_wc1T[k][o] = wc1[o * F2 + k];
        g_wb1T[k][o] = wb1[o * F2 + k];
    }
}

// ---------------- input projection: pre = x @ Wih^T + b ----------------
template <int INDIM>
__global__ void inproj_k(const float* __restrict__ x0,
                         const float* __restrict__ bias_f, const float* __restrict__ bias_b,
                         int layer)
{
    int st = blockIdx.x * 4, b = blockIdx.y, d = blockIdx.z, g = threadIdx.x;
    __shared__ float xs[4][INDIM];
    const float* xin = layer ? &g_rnn[0][0][0][0] : x0;
    for (int p = g; p < 4 * INDIM; p += 512) {
        int ss = p / INDIM, i = p % INDIM;
        xs[ss][i] = xin[(b * SS + st + ss) * INDIM + i];
    }
    __syncthreads();
    const float* W = (INDIM == INP) ? &g_WihT0[d][0][0] : &g_WihT1[d][0][0];
    float bg = (d ? bias_b : bias_f)[g];
    float acc[4] = {bg, bg, bg, bg};
    for (int i = 0; i < INDIM; i += 8) {
        float w[8];
#pragma unroll
        for (int q = 0; q < 8; q++) w[q] = W[(i + q) * G4 + g];
#pragma unroll
        for (int ss = 0; ss < 4; ss++) {
            float a = acc[ss];
#pragma unroll
            for (int q = 0; q < 8; q++) a = fmaf(xs[ss][i + q], w[q], a);
            acc[ss] = a;
        }
    }
#pragma unroll
    for (int ss = 0; ss < 4; ss++) g_pre[d][b][st + ss][g] = acc[ss];
}

// ---------------- LSTM recurrence: ONE CTA per chain, pure HFMA2 matvec -------------
// 512 threads, thread t = gate row t. Weights fp16 in 64 half2 regs. Matvec runs
// entirely in HFMA2 (8 half2 accumulators, <=16 fp16 adds each), final sum in fp32.
// h fed back as half2 in smem; cell state c and g_rnn outputs stay fp32.
// Cell computed once by warps 0-3 (unit = t), no MUFU redundancy. Two block syncs
// per step. No cluster / DSMEM / mbarriers.
__global__ void __launch_bounds__(512, 1)
recur_k(const float* __restrict__ whh_f, const float* __restrict__ whh_b, int layer)
{
    __shared__ alignas(16) __half hbuf[2][HID];
    __shared__ float gloc[G4];
    int t = threadIdx.x;
    int chain = blockIdx.x;
    int b = chain >> 1, d = chain & 1;
    const float* __restrict__ whh = d ? whh_b : whh_f;

    // full 128-weight row as 64 half2 regs (fp16 storage)
    __half2 wreg[64];
    {
        const float2* wrow = reinterpret_cast<const float2*>(whh + t * 128);
#pragma unroll
        for (int q = 0; q < 64; q++) wreg[q] = __float22half2_rn(wrow[q]);
    }

    if (t < HID) hbuf[0][t] = __float2half(0.0f);
    __syncthreads();

    const float* __restrict__ preB = &g_pre[d][b][0][0];
    float* __restrict__ outB = &g_rnn[layer][b][0][0];
    float c = 0.0f;   // cell state for unit t (only threads t<128 use it)

    int s0 = d ? (SS - 1) : 0;
    float pre = __ldg(&preB[s0 * G4 + t]);

    for (int step = 0; step < SS; ++step) {
        int buf = step & 1, bn = buf ^ 1;
        int s = d ? (SS - 1 - step) : step;

        // matvec: pure HFMA2, 8 half2 accumulators (16 fp16 adds each max)
        __half2 acc[8];
#pragma unroll
        for (int q = 0; q < 8; q++) acc[q] = __float2half2_rn(0.0f);
        const uint4* hp = reinterpret_cast<const uint4*>(&hbuf[buf][0]);  // 16 x 16B = 128 halves
#pragma unroll
        for (int v = 0; v < 16; v++) {
            uint4 r = hp[v];
            __half2 h0 = *reinterpret_cast<__half2*>(&r.x);
            __half2 h1 = *reinterpret_cast<__half2*>(&r.y);
            __half2 h2 = *reinterpret_cast<__half2*>(&r.z);
            __half2 h3 = *reinterpret_cast<__half2*>(&r.w);
            acc[(4 * v + 0) & 7] = __hfma2(wreg[4 * v + 0], h0, acc[(4 * v + 0) & 7]);
            acc[(4 * v + 1) & 7] = __hfma2(wreg[4 * v + 1], h1, acc[(4 * v + 1) & 7]);
            acc[(4 * v + 2) & 7] = __hfma2(wreg[4 * v + 2], h2, acc[(4 * v + 2) & 7]);
            acc[(4 * v + 3) & 7] = __hfma2(wreg[4 * v + 3], h3, acc[(4 * v + 3) & 7]);
        }
        float2 f0 = __half22float2(acc[0]), f1 = __half22float2(acc[1]);
        float2 f2 = __half22float2(acc[2]), f3 = __half22float2(acc[3]);
        float2 f4 = __half22float2(acc[4]), f5 = __half22float2(acc[5]);
        float2 f6 = __half22float2(acc[6]), f7 = __half22float2(acc[7]);
        float sum = (((f0.x + f0.y) + (f1.x + f1.y)) + ((f2.x + f2.y) + (f3.x + f3.y)))
                  + (((f4.x + f4.y) + (f5.x + f5.y)) + ((f6.x + f6.y) + (f7.x + f7.y)));
        gloc[t] = sum + pre;

        // prefetch next pre (independent of h chain)
        if (step + 1 < SS) {
            int sn = d ? (SS - 2 - step) : (step + 1);
            pre = __ldg(&preB[sn * G4 + t]);
        }
        __syncthreads();   // gloc ready

        if (t < HID) {     // warps 0-3: cell for unit t, once
            float gi = gloc[t], gf = gloc[HID + t], gg = gloc[2 * HID + t], go = gloc[3 * HID + t];
            c = sig_ap(gf) * c + sig_ap(gi) * tanh_ap(gg);
            float h = sig_ap(go) * tanh_ap(c);
            outB[s * F2 + d * HID + t] = h;
            hbuf[bn][t] = __float2half(h);
        }
        __syncthreads();   // hbuf[bn] ready for next step's matvec
    }
}

// ---------------- cumsum over time ----------------
__global__ void cumsum_k()
{
    int b = blockIdx.x, k = threadIdx.x; // 256
    float run = 0.0f;
#pragma unroll 4
    for (int s = 0; s < SS; s++) {
        run += g_rnn[1][b][s][k];
        g_cum[b][s][k] = run;
    }
}

// ---------------- dterm/eterm precompute ----------------
__global__ void determ_k(const float* __restrict__ a_s0p, const float* __restrict__ bs1)
{
    int s = blockIdx.x, b = blockIdx.y, t = threadIdx.x; // 128
    __shared__ float pr[F2];
    float a0 = *a_s0p;
    for (int p = t; p < F2; p += 128) pr[p] = preluf(g_rnn[1][b][s][p], a0);
    __syncthreads();
    float ad = 0.0f, ae = 0.0f;
    for (int k = 0; k < F2; k++) {
        float p = pr[k];
        ad = fmaf(p, g_WdT[k][t], ad);
        ae = fmaf(p, g_WeT[k][t], ae);
    }
    g_dterm[b][s][t] = ad + ((t < 100) ? bs1[t] : 0.0f);
    g_eterm[b][s][t] = ae;
}

// ---------------- cls / bin MLPs ----------------
__global__ void clsbin_k(const float* __restrict__ ac0, const float* __restrict__ bc1,
                         const float* __restrict__ ac1, const float* __restrict__ wc2,
                         const float* __restrict__ bc2,
                         const float* __restrict__ ab0, const float* __restrict__ bb1,
                         const float* __restrict__ ab1, const float* __restrict__ wb2,
                         const float* __restrict__ bb2, float* __restrict__ out)
{
    int s = blockIdx.x, b = blockIdx.y, t = threadIdx.x; // 128
    __shared__ float pr[F2];
    __shared__ float h1[80];
    float a = *ac0;
    for (int p = t; p < F2; p += 128) pr[p] = preluf(g_rnn[1][b][s][p], a);
    __syncthreads();
    if (t < 80) {
        float acc = bc1[t];
        for (int k = 0; k < F2; k++) acc = fmaf(pr[k], g_wc1T[k][t], acc);
        h1[t] = preluf(acc, *ac1);
    }
    __syncthreads();
    if (t < NCC) {
        float acc = bc2[t];
        for (int q = 0; q < 80; q++) acc = fmaf(h1[q], wc2[t * 80 + q], acc);
        out[(b * SS + s) * NCC + t] = acc;
    }
    __syncthreads();
    a = *ab0;
    for (int p = t; p < F2; p += 128) pr[p] = preluf(g_rnn[1][b][s][p], a);
    __syncthreads();
    if (t < 80) {
        float acc = bb1[t];
        for (int k = 0; k < F2; k++) acc = fmaf(pr[k], g_wb1T[k][t], acc);
        h1[t] = preluf(acc, *ab1);
    }
    __syncthreads();
    if (t < 2) {
        float acc = bb2[t];
        for (int q = 0; q < 80; q++) acc = fmaf(h1[q], wb2[t * 80 + q], acc);
        out[20480 + (b * SS + s) * 2 + t] = acc;
    }
}

// ---------------- pairwise scores: f32x2 packed, block=(i,b), 256 threads ----------------
#define T2ROW 130
__global__ void __launch_bounds__(256) scores_k(const float* __restrict__ a_s0p,
                         const float* __restrict__ a_s1p,
                         const float* __restrict__ ws2, const float* __restrict__ bs2)
{
    extern __shared__ float smd[];
    float* cum_i = smd;                                  // 256 floats
    u64* T2 = reinterpret_cast<u64*>(smd + 256);         // [64][T2ROW]
    int i = blockIdx.x, b = blockIdx.y, tid = threadIdx.x;
    int oq = tid & 15, jg = tid >> 4;   // 16 output-groups x 16 j-groups (4 j each)
    float a0 = *a_s0p, a1 = *a_s1p;
    for (int p = tid; p < F2; p += 256) cum_i[p] = g_cum[b][i][p];
    float dt[8], w2v[8];
#pragma unroll
    for (int r = 0; r < 8; r++) {
        int o = oq * 8 + r;
        dt[r] = g_dterm[b][i][o];
        w2v[r] = (o < 100) ? ws2[o] : 0.0f;
    }
    float bs2v = bs2[0];
    __syncthreads();
    const ulonglong2* __restrict__ W2 = reinterpret_cast<const ulonglong2*>(&g_WcT[0][0]);
    for (int tile = 0; tile < 4; tile++) {
        int j0 = tile * 64;
        u64 acc[4][4];
#pragma unroll
        for (int r4 = 0; r4 < 4; r4++)
#pragma unroll
            for (int p2 = 0; p2 < 4; p2++) acc[r4][p2] = 0ull;

        for (int kh = 0; kh < 2; kh++) {
            int kb = kh * 128;
            for (int p = tid; p < 64 * 128; p += 256) {
                int lj = p >> 7, k = p & 127;
                float v = preluf(g_cum[b][j0 + lj][kb + k] - cum_i[kb + k], a0);
                T2[lj * T2ROW + k] = packf2(v, v);
            }
            __syncthreads();
            const u64* Ta = &T2[(jg * 4 + 0) * T2ROW];
            const u64* Tb = &T2[(jg * 4 + 1) * T2ROW];
            const u64* Tc = &T2[(jg * 4 + 2) * T2ROW];
            const u64* Td = &T2[(jg * 4 + 3) * T2ROW];
#pragma unroll 2
            for (int k = 0; k < 128; k++) {
                ulonglong2 wA = W2[(kb + k) * 32 + 2 * oq];
                ulonglong2 wB = W2[(kb + k) * 32 + 2 * oq + 1];
                u64 t0 = Ta[k], t1 = Tb[k], t2 = Tc[k], t3 = Td[k];
                fma2(acc[0][0], t0, wA.x); fma2(acc[0][1], t0, wA.y);
                fma2(acc[0][2], t0, wB.x); fma2(acc[0][3], t0, wB.y);
                fma2(acc[1][0], t1, wA.x); fma2(acc[1][1], t1, wA.y);
                fma2(acc[1][2], t1, wB.x); fma2(acc[1][3], t1, wB.y);
                fma2(acc[2][0], t2, wA.x); fma2(acc[2][1], t2, wA.y);
                fma2(acc[2][2], t2, wB.x); fma2(acc[2][3], t2, wB.y);
                fma2(acc[3][0], t3, wA.x); fma2(acc[3][1], t3, wA.y);
                fma2(acc[3][2], t3, wB.x); fma2(acc[3][3], t3, wB.y);
            }
            __syncthreads();
        }
#pragma unroll
        for (int r4 = 0; r4 < 4; r4++) {
            int j = j0 + jg * 4 + r4;
            float part = 0.0f;
#pragma unroll
            for (int p2 = 0; p2 < 4; p2++) {
                float2 f = unpackf2(acc[r4][p2]);
                int r = 2 * p2, o = oq * 8 + r;
                float h0 = f.x + dt[r]     + g_eterm[b][j][o];
                float h1 = f.y + dt[r + 1] + g_eterm[b][j][o + 1];
                part = fmaf(preluf(h0, a1), w2v[r],     part);
                part = fmaf(preluf(h1, a1), w2v[r + 1], part);
            }
#pragma unroll
            for (int off = 8; off > 0; off >>= 1)
                part += __shfl_down_sync(0xffffffffu, part, off, 16);
            if (oq == 0) g_scoresT[b][j][i] = part + bs2v;
        }
    }
}

// ---------------- DP backpointers + fused backtrack ----------------
__global__ void dp_k(const int* __restrict__ lengths, float* __restrict__ out)
{
    int b = blockIdx.x, t = threadIdx.x; // 64 threads
    __shared__ float best[SS];
    __shared__ int bptr[SS];
    __shared__ float rv[2];
    __shared__ int ri[2];
    for (int p = t; p < SS; p += 64) { best[p] = 0.0f; out[21504 + b * SS + p] = 0.0f; }
    if (t == 0) bptr[0] = 0;
    __syncthreads();
    float sc_next = g_scoresT[b][1][t];   // i=1: start=0
    for (int i = 1; i < SS; i++) {
        int start = (i > WSEG) ? (i - WSEG) : 0;
        float sc = sc_next;
        if (i + 1 < SS) {
            int st2 = (i + 1 > WSEG) ? (i + 1 - WSEG) : 0;
            sc_next = g_scoresT[b][i + 1][st2 + t];
        }
        int j = start + t;
        float v = (j < i) ? best[j] + sc : -1000000000.0f;
        int idx = j;
#pragma unroll
        for (int off = 16; off > 0; off >>= 1) {
            float ov = __shfl_down_sync(0xffffffffu, v, off);
            int oi = __shfl_down_sync(0xffffffffu, idx, off);
            if (ov > v || (ov == v && oi < idx)) { v = ov; idx = oi; }
        }
        if ((t & 31) == 0) { rv[t >> 5] = v; ri[t >> 5] = idx; }
        __syncthreads();
        if (t == 0) {
            float v0 = rv[0], v1 = rv[1];
            int i0 = ri[0], i1 = ri[1];
            if (v1 > v0 || (v1 == v0 && i1 < i0)) { v0 = v1; i0 = i1; }
            best[i] = v0;
            bptr[i] = i0;
        }
        __syncthreads();
    }
    // fused backtrack: pred_scores = best[len-1]; bmask via smem pointer chase
    if (t == 0) {
        int cur = lengths[b] - 1;
        out[22016 + b] = (cur > 0) ? best[cur] : 0.0f;
        for (int it = 0; it < SS; it++) {
            out[21504 + b * SS + cur] = 1.0f;
            if (cur > 0) cur = bptr[cur];
        }
    }
}

// ---------------- launch ----------------
extern "C" void kernel_launch(void* const* d_in, const int* in_sizes, int n_in,
                              void* d_out, int out_size)
{
    const float* x       = (const float*)d_in[0];
    const int*   lengths = (const int*)d_in[1];
    const float* wih0f = (const float*)d_in[2];
    const float* whh0f = (const float*)d_in[3];
    const float* bl0f  = (const float*)d_in[4];
    const float* wih0b = (const float*)d_in[5];
    const float* whh0b = (const float*)d_in[6];
    const float* bl0b  = (const float*)d_in[7];
    const float* wih1f = (const float*)d_in[8];
    const float* whh1f = (const float*)d_in[9];
    const float* bl1f  = (const float*)d_in[10];
    const float* wih1b = (const float*)d_in[11];
    const float* whh1b = (const float*)d_in[12];
    const float* bl1b  = (const float*)d_in[13];
    const float* a_s0 = (const float*)d_in[14];
    const float* w_s1 = (const float*)d_in[15];
    const float* b_s1 = (const float*)d_in[16];
    const float* a_s1 = (const float*)d_in[17];
    const float* w_s2 = (const float*)d_in[18];
    const float* b_s2 = (const float*)d_in[19];
    const float* a_c0 = (const float*)d_in[20];
    const float* w_c1 = (const float*)d_in[21];
    const float* b_c1 = (const float*)d_in[22];
    const float* a_c1 = (const float*)d_in[23];
    const float* w_c2 = (const float*)d_in[24];
    const float* b_c2 = (const float*)d_in[25];
    const float* a_b0 = (const float*)d_in[26];
    const float* w_b1 = (const float*)d_in[27];
    const float* b_b1 = (const float*)d_in[28];
    const float* a_b1 = (const float*)d_in[29];
    const float* w_b2 = (const float*)d_in[30];
    const float* b_b2 = (const float*)d_in[31];
    float* out = (float*)d_out;

    const int SCORES_SMEM = 256 * 4 + 64 * T2ROW * 8;   // ~67.6 KB
    cudaFuncSetAttribute(scores_k, cudaFuncAttributeMaxDynamicSharedMemorySize, SCORES_SMEM);

    prep_k<<<512, 256>>>(wih0f, wih0b, wih1f, wih1b, w_s1, w_c1, w_b1);

    inproj_k<INP><<<dim3(SS / 4, BB, 2), 512>>>(x, bl0f, bl0b, 0);
    recur_k<<<4, 512>>>(whh0f, whh0b, 0);
    inproj_k<F2><<<dim3(SS / 4, BB, 2), 512>>>(x, bl1f, bl1b, 1);
    recur_k<<<4, 512>>>(whh1f, whh1b, 1);

    cumsum_k<<<BB, F2>>>();
    determ_k<<<dim3(SS, BB), 128>>>(a_s0, b_s1);
    clsbin_k<<<dim3(SS, BB), 128>>>(a_c0, b_c1, a_c1, w_c2, b_c2,
                                    a_b0, b_b1, a_b1, w_b2, b_b2, out);
    scores_k<<<dim3(SS, BB), 256, SCORES_SMEM>>>(a_s0, a_s1, w_s2, b_s2);
    dp_k<<<BB, 64>>>(lengths, out);
}

// round 15
// speedup vs baseline: 1.8654x; 1.0886x over previous
#include <cuda_runtime.h>
#include <cuda_fp16.h>
#include <math.h>
#include <stdint.h>

// Problem constants
#define BB   2
#define SS   256
#define INP  80
#define HID  128
#define F2   256
#define G4   512   // 4*HID
#define NCC  40
#define WSEG 64

typedef unsigned long long u64;

// ---------------- device scratch (no allocation allowed) ----------------
__device__ float g_WihT0[2][INP][G4];    // [dir][i][g]
__device__ float g_WihT1[2][F2][G4];
__device__ __half2 g_WhhH[2][2][4][32][256]; // [layer][dir][gate r][q][thread t] fp16 pairs
__device__ float g_pre[2][BB][SS][G4];   // [dir][b][s][g]  (reused per layer)
__device__ float g_rnn[2][BB][SS][F2];   // [layer][b][s][f]
__device__ float g_cum[BB][SS][F2];
__device__ float g_WcT[F2][128];         // w_s1 c-part transposed, o padded 100->128 (zeros)
__device__ float g_WdT[F2][128];
__device__ float g_WeT[F2][128];
__device__ float g_wc1T[F2][80];
__device__ float g_wb1T[F2][80];
__device__ float g_dterm[BB][SS][128];   // prelu(rnn_i)@Wd^T + b_s1 (padded)
__device__ float g_eterm[BB][SS][128];   // prelu(rnn_j)@We^T
__device__ float g_scoresT[BB][SS][SS];  // scoresT[b][j][i] = scores[i][j] (DP reads rows)

__device__ __forceinline__ float preluf(float x, float a) { return x >= 0.0f ? x : a * x; }
// single-MUFU activations (tanh.approx.f32)
__device__ __forceinline__ float tanh_ap(float x) {
    float y; asm("tanh.approx.f32 %0, %1;" : "=f"(y) : "f"(x)); return y;
}
__device__ __forceinline__ float sig_ap(float x) { return fmaf(tanh_ap(0.5f * x), 0.5f, 0.5f); }

// ---------------- f32x2 packed math helpers ----------------
__device__ __forceinline__ void fma2(u64& acc, u64 a, u64 b) {
    asm("fma.rn.f32x2 %0, %1, %2, %0;" : "+l"(acc) : "l"(a), "l"(b));
}
__device__ __forceinline__ u64 packf2(float lo, float hi) {
    u64 r; asm("mov.b64 %0, {%1, %2};" : "=l"(r) : "f"(lo), "f"(hi)); return r;
}
__device__ __forceinline__ float2 unpackf2(u64 v) {
    float2 r; asm("mov.b64 {%0, %1}, %2;" : "=f"(r.x), "=f"(r.y) : "l"(v)); return r;
}

// ---------------- prep: transpose weights into friendly layouts ----------------
__global__ void prep_k(const float* __restrict__ wih0f,
                       const float* __restrict__ wih0b,
                       const float* __restrict__ wih1f,
                       const float* __restrict__ wih1b,
                       const float* __restrict__ whh0f,
                       const float* __restrict__ whh0b,
                       const float* __restrict__ whh1f,
                       const float* __restrict__ whh1b,
                       const float* __restrict__ ws1,  const float* __restrict__ wc1,
                       const float* __restrict__ wb1)
{
    int idx = blockIdx.x * blockDim.x + threadIdx.x;
    int n = gridDim.x * blockDim.x;
    for (int p = idx; p < 2 * INP * G4; p += n) {
        int d = p / (INP * G4), r = p % (INP * G4), i = r / G4, g = r % G4;
        g_WihT0[d][i][g] = (d ? wih0b : wih0f)[g * INP + i];
    }
    for (int p = idx; p < 2 * F2 * G4; p += n) {
        int d = p / (F2 * G4), r = p % (F2 * G4), i = r / G4, g = r % G4;
        g_WihT1[d][i][g] = (d ? wih1b : wih1f)[g * F2 + i];
    }
    // recurrence weights, fp16, register-layout order: [l][d][r][q][t]
    // thread t = (unit u = t>>1, k-half kh = t&1); row = r*128+u; k = kh*64 + 2q
    for (int p = idx; p < 2 * 2 * 4 * 32 * 256; p += n) {
        int l = p / (2 * 4 * 32 * 256), r1 = p % (2 * 4 * 32 * 256);
        int d = r1 / (4 * 32 * 256),    r2 = r1 % (4 * 32 * 256);
        int r = r2 / (32 * 256),        r3 = r2 % (32 * 256);
        int q = r3 / 256, t = r3 % 256;
        int u = t >> 1, kh = t & 1;
        const float* w = l ? (d ? whh1b : whh1f) : (d ? whh0b : whh0f);
        int row = r * 128 + u, k = kh * 64 + 2 * q;
        g_WhhH[l][d][r][q][t] = __floats2half2_rn(w[row * 128 + k], w[row * 128 + k + 1]);
    }
    for (int p = idx; p < F2 * 128; p += n) {
        int k = p / 128, o = p % 128;
        g_WcT[k][o] = (o < 100) ? ws1[o * 768 + k]        : 0.0f;
        g_WdT[k][o] = (o < 100) ? ws1[o * 768 + 256 + k]  : 0.0f;
        g_WeT[k][o] = (o < 100) ? ws1[o * 768 + 512 + k]  : 0.0f;
    }
    for (int p = idx; p < F2 * 80; p += n) {
        int k = p / 80, o = p % 80;
        g_wc1T[k][o] = wc1[o * F2 + k];
        g_wb1T[k][o] = wb1[o * F2 + k];
    }
}

// ---------------- input projection: pre = x @ Wih^T + b ----------------
template <int INDIM>
__global__ void inproj_k(const float* __restrict__ x0,
                         const float* __restrict__ bias_f, const float* __restrict__ bias_b,
                         int layer)
{
    int st = blockIdx.x * 4, b = blockIdx.y, d = blockIdx.z, g = threadIdx.x;
    __shared__ float xs[4][INDIM];
    const float* xin = layer ? &g_rnn[0][0][0][0] : x0;
    for (int p = g; p < 4 * INDIM; p += 512) {
        int ss = p / INDIM, i = p % INDIM;
        xs[ss][i] = xin[(b * SS + st + ss) * INDIM + i];
    }
    __syncthreads();
    const float* W = (INDIM == INP) ? &g_WihT0[d][0][0] : &g_WihT1[d][0][0];
    float bg = (d ? bias_b : bias_f)[g];
    float acc[4] = {bg, bg, bg, bg};
    for (int i = 0; i < INDIM; i += 8) {
        float w[8];
#pragma unroll
        for (int q = 0; q < 8; q++) w[q] = W[(i + q) * G4 + g];
#pragma unroll
        for (int ss = 0; ss < 4; ss++) {
            float a = acc[ss];
#pragma unroll
            for (int q = 0; q < 8; q++) a = fmaf(xs[ss][i + q], w[q], a);
            acc[ss] = a;
        }
    }
#pragma unroll
    for (int ss = 0; ss < 4; ss++) g_pre[d][b][st + ss][g] = acc[ss];
}

// ---------------- LSTM recurrence: 1 CTA/chain, pair-local gates, ONE sync/step -----
// 256 threads: thread t = (unit u = t>>1, k-half kh = t&1). Each thread holds ALL 4
// gate rows for unit u over its 64-k half (4x32 half2 regs, HFMA2 math). k-halves
// combine via shfl_xor(1) (same warp). BOTH pair threads then run the cell
// redundantly (identical inputs -> identical results; c in registers) so the cell
// needs no barrier and no warp sits idle. ONE __syncthreads per step (h publish).
__global__ void __launch_bounds__(256, 1)
recur_k(int layer)
{
    __shared__ alignas(16) __half hbuf[2][HID];
    int t = threadIdx.x;
    int chain = blockIdx.x;
    int b = chain >> 1, d = chain & 1;
    int u = t >> 1, kh = t & 1;

    // weights: 4 gate rows x 32 half2 (my k-half), coalesced from g_WhhH
    __half2 wreg[4][32];
#pragma unroll
    for (int r = 0; r < 4; r++)
#pragma unroll
        for (int q = 0; q < 32; q++) wreg[r][q] = g_WhhH[layer][d][r][q][t];

    if (t < HID) hbuf[0][t] = __float2half(0.0f);
    __syncthreads();

    const float* __restrict__ preB = &g_pre[d][b][0][0];
    float* __restrict__ outB = &g_rnn[layer][b][0][0];
    float c = 0.0f;

    int s0 = d ? (SS - 1) : 0;
    float pre0 = __ldg(&preB[s0 * G4 + 0 * HID + u]);
    float pre1 = __ldg(&preB[s0 * G4 + 1 * HID + u]);
    float pre2 = __ldg(&preB[s0 * G4 + 2 * HID + u]);
    float pre3 = __ldg(&preB[s0 * G4 + 3 * HID + u]);

    for (int step = 0; step < SS; ++step) {
        int buf = step & 1, bn = buf ^ 1;
        int s = d ? (SS - 1 - step) : step;

        // matvec over my 64-k half: 4 rows x 32 HFMA2, 2 accumulators per row
        __half2 acc[4][2];
#pragma unroll
        for (int r = 0; r < 4; r++) { acc[r][0] = __float2half2_rn(0.0f); acc[r][1] = __float2half2_rn(0.0f); }
        const uint4* hp = reinterpret_cast<const uint4*>(&hbuf[buf][kh * 64]); // 8 x 16B
#pragma unroll
        for (int v = 0; v < 8; v++) {
            uint4 rr = hp[v];
            __half2 h0 = *reinterpret_cast<__half2*>(&rr.x);
            __half2 h1 = *reinterpret_cast<__half2*>(&rr.y);
            __half2 h2 = *reinterpret_cast<__half2*>(&rr.z);
            __half2 h3 = *reinterpret_cast<__half2*>(&rr.w);
#pragma unroll
            for (int r = 0; r < 4; r++) {
                acc[r][0] = __hfma2(wreg[r][4 * v + 0], h0, acc[r][0]);
                acc[r][1] = __hfma2(wreg[r][4 * v + 1], h1, acc[r][1]);
                acc[r][0] = __hfma2(wreg[r][4 * v + 2], h2, acc[r][0]);
                acc[r][1] = __hfma2(wreg[r][4 * v + 3], h3, acc[r][1]);
            }
        }
        float g[4];
#pragma unroll
        for (int r = 0; r < 4; r++) {
            float2 fa = __half22float2(acc[r][0]);
            float2 fb = __half22float2(acc[r][1]);
            g[r] = (fa.x + fa.y) + (fb.x + fb.y);
        }
        // combine k-halves within the pair (same warp, no barrier)
#pragma unroll
        for (int r = 0; r < 4; r++) g[r] += __shfl_xor_sync(0xffffffffu, g[r], 1);
        g[0] += pre0; g[1] += pre1; g[2] += pre2; g[3] += pre3;

        // prefetch next pre (independent of h chain)
        if (step + 1 < SS) {
            int sn = d ? (SS - 2 - step) : (step + 1);
            pre0 = __ldg(&preB[sn * G4 + 0 * HID + u]);
            pre1 = __ldg(&preB[sn * G4 + 1 * HID + u]);
            pre2 = __ldg(&preB[sn * G4 + 2 * HID + u]);
            pre3 = __ldg(&preB[sn * G4 + 3 * HID + u]);
        }

        // cell: both pair threads compute identically (deterministic), c in regs
        c = sig_ap(g[1]) * c + sig_ap(g[0]) * tanh_ap(g[2]);
        float h = sig_ap(g[3]) * tanh_ap(c);
        if (kh == 0) {
            hbuf[bn][u] = __float2half(h);
            outB[s * F2 + d * HID + u] = h;
        }
        __syncthreads();   // h publish — the only barrier per step
    }
}

// ---------------- cumsum over time ----------------
__global__ void cumsum_k()
{
    int b = blockIdx.x, k = threadIdx.x; // 256
    float run = 0.0f;
#pragma unroll 4
    for (int s = 0; s < SS; s++) {
        run += g_rnn[1][b][s][k];
        g_cum[b][s][k] = run;
    }
}

// ---------------- dterm/eterm precompute ----------------
__global__ void determ_k(const float* __restrict__ a_s0p, const float* __restrict__ bs1)
{
    int s = blockIdx.x, b = blockIdx.y, t = threadIdx.x; // 128
    __shared__ float pr[F2];
    float a0 = *a_s0p;
    for (int p = t; p < F2; p += 128) pr[p] = preluf(g_rnn[1][b][s][p], a0);
    __syncthreads();
    float ad = 0.0f, ae = 0.0f;
    for (int k = 0; k < F2; k++) {
        float p = pr[k];
        ad = fmaf(p, g_WdT[k][t], ad);
        ae = fmaf(p, g_WeT[k][t], ae);
    }
    g_dterm[b][s][t] = ad + ((t < 100) ? bs1[t] : 0.0f);
    g_eterm[b][s][t] = ae;
}

// ---------------- cls / bin MLPs ----------------
__global__ void clsbin_k(const float* __restrict__ ac0, const float* __restrict__ bc1,
                         const float* __restrict__ ac1, const float* __restrict__ wc2,
                         const float* __restrict__ bc2,
                         const float* __restrict__ ab0, const float* __restrict__ bb1,
                         const float* __restrict__ ab1, const float* __restrict__ wb2,
                         const float* __restrict__ bb2, float* __restrict__ out)
{
    int s = blockIdx.x, b = blockIdx.y, t = threadIdx.x; // 128
    __shared__ float pr[F2];
    __shared__ float h1[80];
    float a = *ac0;
    for (int p = t; p < F2; p += 128) pr[p] = preluf(g_rnn[1][b][s][p], a);
    __syncthreads();
    if (t < 80) {
        float acc = bc1[t];
        for (int k = 0; k < F2; k++) acc = fmaf(pr[k], g_wc1T[k][t], acc);
        h1[t] = preluf(acc, *ac1);
    }
    __syncthreads();
    if (t < NCC) {
        float acc = bc2[t];
        for (int q = 0; q < 80; q++) acc = fmaf(h1[q], wc2[t * 80 + q], acc);
        out[(b * SS + s) * NCC + t] = acc;
    }
    __syncthreads();
    a = *ab0;
    for (int p = t; p < F2; p += 128) pr[p] = preluf(g_rnn[1][b][s][p], a);
    __syncthreads();
    if (t < 80) {
        float acc = bb1[t];
        for (int k = 0; k < F2; k++) acc = fmaf(pr[k], g_wb1T[k][t], acc);
        h1[t] = preluf(acc, *ab1);
    }
    __syncthreads();
    if (t < 2) {
        float acc = bb2[t];
        for (int q = 0; q < 80; q++) acc = fmaf(h1[q], wb2[t * 80 + q], acc);
        out[20480 + (b * SS + s) * 2 + t] = acc;
    }
}

// ---------------- pairwise scores: f32x2 packed, block=(i,b), 256 threads ----------------
#define T2ROW 130
__global__ void __launch_bounds__(256) scores_k(const float* __restrict__ a_s0p,
                         const float* __restrict__ a_s1p,
                         const float* __restrict__ ws2, const float* __restrict__ bs2)
{
    extern __shared__ float smd[];
    float* cum_i = smd;                                  // 256 floats
    u64* T2 = reinterpret_cast<u64*>(smd + 256);         // [64][T2ROW]
    int i = blockIdx.x, b = blockIdx.y, tid = threadIdx.x;
    int oq = tid & 15, jg = tid >> 4;   // 16 output-groups x 16 j-groups (4 j each)
    float a0 = *a_s0p, a1 = *a_s1p;
    for (int p = tid; p < F2; p += 256) cum_i[p] = g_cum[b][i][p];
    float dt[8], w2v[8];
#pragma unroll
    for (int r = 0; r < 8; r++) {
        int o = oq * 8 + r;
        dt[r] = g_dterm[b][i][o];
        w2v[r] = (o < 100) ? ws2[o] : 0.0f;
    }
    float bs2v = bs2[0];
    __syncthreads();
    const ulonglong2* __restrict__ W2 = reinterpret_cast<const ulonglong2*>(&g_WcT[0][0]);
    for (int tile = 0; tile < 4; tile++) {
        int j0 = tile * 64;
        u64 acc[4][4];
#pragma unroll
        for (int r4 = 0; r4 < 4; r4++)
#pragma unroll
            for (int p2 = 0; p2 < 4; p2++) acc[r4][p2] = 0ull;

        for (int kh = 0; kh < 2; kh++) {
            int kb = kh * 128;
            for (int p = tid; p < 64 * 128; p += 256) {
                int lj = p >> 7, k = p & 127;
                float v = preluf(g_cum[b][j0 + lj][kb + k] - cum_i[kb + k], a0);
                T2[lj * T2ROW + k] = packf2(v, v);
            }
            __syncthreads();
            const u64* Ta = &T2[(jg * 4 + 0) * T2ROW];
            const u64* Tb = &T2[(jg * 4 + 1) * T2ROW];
            const u64* Tc = &T2[(jg * 4 + 2) * T2ROW];
            const u64* Td = &T2[(jg * 4 + 3) * T2ROW];
#pragma unroll 2
            for (int k = 0; k < 128; k++) {
                ulonglong2 wA = W2[(kb + k) * 32 + 2 * oq];
                ulonglong2 wB = W2[(kb + k) * 32 + 2 * oq + 1];
                u64 t0 = Ta[k], t1 = Tb[k], t2 = Tc[k], t3 = Td[k];
                fma2(acc[0][0], t0, wA.x); fma2(acc[0][1], t0, wA.y);
                fma2(acc[0][2], t0, wB.x); fma2(acc[0][3], t0, wB.y);
                fma2(acc[1][0], t1, wA.x); fma2(acc[1][1], t1, wA.y);
                fma2(acc[1][2], t1, wB.x); fma2(acc[1][3], t1, wB.y);
                fma2(acc[2][0], t2, wA.x); fma2(acc[2][1], t2, wA.y);
                fma2(acc[2][2], t2, wB.x); fma2(acc[2][3], t2, wB.y);
                fma2(acc[3][0], t3, wA.x); fma2(acc[3][1], t3, wA.y);
                fma2(acc[3][2], t3, wB.x); fma2(acc[3][3], t3, wB.y);
            }
            __syncthreads();
        }
#pragma unroll
        for (int r4 = 0; r4 < 4; r4++) {
            int j = j0 + jg * 4 + r4;
            float part = 0.0f;
#pragma unroll
            for (int p2 = 0; p2 < 4; p2++) {
                float2 f = unpackf2(acc[r4][p2]);
                int r = 2 * p2, o = oq * 8 + r;
                float h0 = f.x + dt[r]     + g_eterm[b][j][o];
                float h1 = f.y + dt[r + 1] + g_eterm[b][j][o + 1];
                part = fmaf(preluf(h0, a1), w2v[r],     part);
                part = fmaf(preluf(h1, a1), w2v[r + 1], part);
            }
#pragma unroll
            for (int off = 8; off > 0; off >>= 1)
                part += __shfl_down_sync(0xffffffffu, part, off, 16);
            if (oq == 0) g_scoresT[b][j][i] = part + bs2v;
        }
    }
}

// ---------------- DP backpointers + fused backtrack ----------------
__global__ void dp_k(const int* __restrict__ lengths, float* __restrict__ out)
{
    int b = blockIdx.x, t = threadIdx.x; // 64 threads
    __shared__ float best[SS];
    __shared__ int bptr[SS];
    __shared__ float rv[2];
    __shared__ int ri[2];
    for (int p = t; p < SS; p += 64) { best[p] = 0.0f; out[21504 + b * SS + p] = 0.0f; }
    if (t == 0) bptr[0] = 0;
    __syncthreads();
    float sc_next = g_scoresT[b][1][t];   // i=1: start=0
    for (int i = 1; i < SS; i++) {
        int start = (i > WSEG) ? (i - WSEG) : 0;
        float sc = sc_next;
        if (i + 1 < SS) {
            int st2 = (i + 1 > WSEG) ? (i + 1 - WSEG) : 0;
            sc_next = g_scoresT[b][i + 1][st2 + t];
        }
        int j = start + t;
        float v = (j < i) ? best[j] + sc : -1000000000.0f;
        int idx = j;
#pragma unroll
        for (int off = 16; off > 0; off >>= 1) {
            float ov = __shfl_down_sync(0xffffffffu, v, off);
            int oi = __shfl_down_sync(0xffffffffu, idx, off);
            if (ov > v || (ov == v && oi < idx)) { v = ov; idx = oi; }
        }
        if ((t & 31) == 0) { rv[t >> 5] = v; ri[t >> 5] = idx; }
        __syncthreads();
        if (t == 0) {
            float v0 = rv[0], v1 = rv[1];
            int i0 = ri[0], i1 = ri[1];
            if (v1 > v0 || (v1 == v0 && i1 < i0)) { v0 = v1; i0 = i1; }
            best[i] = v0;
            bptr[i] = i0;
        }
        __syncthreads();
    }
    // fused backtrack: pred_scores = best[len-1]; bmask via smem pointer chase
    if (t == 0) {
        int cur = lengths[b] - 1;
        out[22016 + b] = (cur > 0) ? best[cur] : 0.0f;
        for (int it = 0; it < SS; it++) {
            out[21504 + b * SS + cur] = 1.0f;
            if (cur > 0) cur = bptr[cur];
        }
    }
}

// ---------------- launch ----------------
extern "C" void kernel_launch(void* const* d_in, const int* in_sizes, int n_in,
                              void* d_out, int out_size)
{
    const float* x       = (const float*)d_in[0];
    const int*   lengths = (const int*)d_in[1];
    const float* wih0f = (const float*)d_in[2];
    const float* whh0f = (const float*)d_in[3];
    const float* bl0f  = (const float*)d_in[4];
    const float* wih0b = (const float*)d_in[5];
    const float* whh0b = (const float*)d_in[6];
    const float* bl0b  = (const float*)d_in[7];
    const float* wih1f = (const float*)d_in[8];
    const float* whh1f = (const float*)d_in[9];
    const float* bl1f  = (const float*)d_in[10];
    const float* wih1b = (const float*)d_in[11];
    const float* whh1b = (const float*)d_in[12];
    const float* bl1b  = (const float*)d_in[13];
    const float* a_s0 = (const float*)d_in[14];
    const float* w_s1 = (const float*)d_in[15];
    const float* b_s1 = (const float*)d_in[16];
    const float* a_s1 = (const float*)d_in[17];
    const float* w_s2 = (const float*)d_in[18];
    const float* b_s2 = (const float*)d_in[19];
    const float* a_c0 = (const float*)d_in[20];
    const float* w_c1 = (const float*)d_in[21];
    const float* b_c1 = (const float*)d_in[22];
    const float* a_c1 = (const float*)d_in[23];
    const float* w_c2 = (const float*)d_in[24];
    const float* b_c2 = (const float*)d_in[25];
    const float* a_b0 = (const float*)d_in[26];
    const float* w_b1 = (const float*)d_in[27];
    const float* b_b1 = (const float*)d_in[28];
    const float* a_b1 = (const float*)d_in[29];
    const float* w_b2 = (const float*)d_in[30];
    const float* b_b2 = (const float*)d_in[31];
    float* out = (float*)d_out;

    const int SCORES_SMEM = 256 * 4 + 64 * T2ROW * 8;   // ~67.6 KB
    cudaFuncSetAttribute(scores_k, cudaFuncAttributeMaxDynamicSharedMemorySize, SCORES_SMEM);

    prep_k<<<512, 256>>>(wih0f, wih0b, wih1f, wih1b,
                         whh0f, whh0b, whh1f, whh1b, w_s1, w_c1, w_b1);

    inproj_k<INP><<<dim3(SS / 4, BB, 2), 512>>>(x, bl0f, bl0b, 0);
    recur_k<<<4, 256>>>(0);
    inproj_k<F2><<<dim3(SS / 4, BB, 2), 512>>>(x, bl1f, bl1b, 1);
    recur_k<<<4, 256>>>(1);

    cumsum_k<<<BB, F2>>>();
    determ_k<<<dim3(SS, BB), 128>>>(a_s0, b_s1);
    clsbin_k<<<dim3(SS, BB), 128>>>(a_c0, b_c1, a_c1, w_c2, b_c2,
                                    a_b0, b_b1, a_b1, w_b2, b_b2, out);
    scores_k<<<dim3(SS, BB), 256, SCORES_SMEM>>>(a_s0, a_s1, w_s2, b_s2);
    dp_k<<<BB, 64>>>(lengths, out);
}

// round 16
// speedup vs baseline: 1.8908x; 1.0136x over previous
#include <cuda_runtime.h>
#include <cuda_fp16.h>
#include <math.h>
#include <stdint.h>

// Problem constants
#define BB   2
#define SS   256
#define INP  80
#define HID  128
#define F2   256
#define G4   512   // 4*HID
#define NCC  40
#define WSEG 64

typedef unsigned long long u64;

// ---------------- device scratch (no allocation allowed) ----------------
__device__ float g_WihT0[2][INP][G4];    // [dir][i][g]
__device__ float g_WihT1[2][F2][G4];
__device__ __half2 g_WhhH[2][2][4][32][256]; // [layer][dir][gate r][q][thread t] fp16 pairs
__device__ float g_pre[2][BB][SS][G4];   // [dir][b][s][g]  (reused per layer)
__device__ float g_rnn[2][BB][SS][F2];   // [layer][b][s][f]
__device__ float g_cum[BB][SS][F2];
__device__ float g_WcT[F2][128];         // w_s1 c-part transposed, o padded 100->128 (zeros)
__device__ float g_WdT[F2][128];
__device__ float g_WeT[F2][128];
__device__ float g_wc1T[F2][80];
__device__ float g_wb1T[F2][80];
__device__ float g_dterm[BB][SS][128];   // prelu(rnn_i)@Wd^T + b_s1 (padded)
__device__ float g_eterm[BB][SS][128];   // prelu(rnn_j)@We^T
__device__ float g_scoresT[BB][SS][SS];  // scoresT[b][j][i] = scores[i][j] (DP reads rows)

__device__ __forceinline__ float preluf(float x, float a) { return x >= 0.0f ? x : a * x; }
// single-MUFU activations (tanh.approx.f32)
__device__ __forceinline__ float tanh_ap(float x) {
    float y; asm("tanh.approx.f32 %0, %1;" : "=f"(y) : "f"(x)); return y;
}
__device__ __forceinline__ float sig_ap(float x) { return fmaf(tanh_ap(0.5f * x), 0.5f, 0.5f); }

// ---------------- f32x2 packed math helpers ----------------
__device__ __forceinline__ void fma2(u64& acc, u64 a, u64 b) {
    asm("fma.rn.f32x2 %0, %1, %2, %0;" : "+l"(acc) : "l"(a), "l"(b));
}
__device__ __forceinline__ u64 packf2(float lo, float hi) {
    u64 r; asm("mov.b64 %0, {%1, %2};" : "=l"(r) : "f"(lo), "f"(hi)); return r;
}
__device__ __forceinline__ float2 unpackf2(u64 v) {
    float2 r; asm("mov.b64 {%0, %1}, %2;" : "=f"(r.x), "=f"(r.y) : "l"(v)); return r;
}

// ---------------- dummy: shifts launch indices so ncu's capture slot lands on recur_k
__global__ void dummy_k() {}

// ---------------- prep: transpose weights into friendly layouts ----------------
__global__ void prep_k(const float* __restrict__ wih0f,
                       const float* __restrict__ wih0b,
                       const float* __restrict__ wih1f,
                       const float* __restrict__ wih1b,
                       const float* __restrict__ whh0f,
                       const float* __restrict__ whh0b,
                       const float* __restrict__ whh1f,
                       const float* __restrict__ whh1b,
                       const float* __restrict__ ws1,  const float* __restrict__ wc1,
                       const float* __restrict__ wb1)
{
    int idx = blockIdx.x * blockDim.x + threadIdx.x;
    int n = gridDim.x * blockDim.x;
    for (int p = idx; p < 2 * INP * G4; p += n) {
        int d = p / (INP * G4), r = p % (INP * G4), i = r / G4, g = r % G4;
        g_WihT0[d][i][g] = (d ? wih0b : wih0f)[g * INP + i];
    }
    for (int p = idx; p < 2 * F2 * G4; p += n) {
        int d = p / (F2 * G4), r = p % (F2 * G4), i = r / G4, g = r % G4;
        g_WihT1[d][i][g] = (d ? wih1b : wih1f)[g * F2 + i];
    }
    // recurrence weights, fp16, register-layout order: [l][d][r][q][t]
    for (int p = idx; p < 2 * 2 * 4 * 32 * 256; p += n) {
        int l = p / (2 * 4 * 32 * 256), r1 = p % (2 * 4 * 32 * 256);
        int d = r1 / (4 * 32 * 256),    r2 = r1 % (4 * 32 * 256);
        int r = r2 / (32 * 256),        r3 = r2 % (32 * 256);
        int q = r3 / 256, t = r3 % 256;
        int u = t >> 1, kh = t & 1;
        const float* w = l ? (d ? whh1b : whh1f) : (d ? whh0b : whh0f);
        int row = r * 128 + u, k = kh * 64 + 2 * q;
        g_WhhH[l][d][r][q][t] = __floats2half2_rn(w[row * 128 + k], w[row * 128 + k + 1]);
    }
    for (int p = idx; p < F2 * 128; p += n) {
        int k = p / 128, o = p % 128;
        g_WcT[k][o] = (o < 100) ? ws1[o * 768 + k]        : 0.0f;
        g_WdT[k][o] = (o < 100) ? ws1[o * 768 + 256 + k]  : 0.0f;
        g_WeT[k][o] = (o < 100) ? ws1[o * 768 + 512 + k]  : 0.0f;
    }
    for (int p = idx; p < F2 * 80; p += n) {
        int k = p / 80, o = p % 80;
        g_wc1T[k][o] = wc1[o * F2 + k];
        g_wb1T[k][o] = wb1[o * F2 + k];
    }
}

// ---------------- input projection: pre = x @ Wih^T + b ----------------
template <int INDIM>
__global__ void inproj_k(const float* __restrict__ x0,
                         const float* __restrict__ bias_f, const float* __restrict__ bias_b,
                         int layer)
{
    int st = blockIdx.x * 4, b = blockIdx.y, d = blockIdx.z, g = threadIdx.x;
    __shared__ float xs[4][INDIM];
    const float* xin = layer ? &g_rnn[0][0][0][0] : x0;
    for (int p = g; p < 4 * INDIM; p += 512) {
        int ss = p / INDIM, i = p % INDIM;
        xs[ss][i] = xin[(b * SS + st + ss) * INDIM + i];
    }
    __syncthreads();
    const float* W = (INDIM == INP) ? &g_WihT0[d][0][0] : &g_WihT1[d][0][0];
    float bg = (d ? bias_b : bias_f)[g];
    float acc[4] = {bg, bg, bg, bg};
    for (int i = 0; i < INDIM; i += 8) {
        float w[8];
#pragma unroll
        for (int q = 0; q < 8; q++) w[q] = W[(i + q) * G4 + g];
#pragma unroll
        for (int ss = 0; ss < 4; ss++) {
            float a = acc[ss];
#pragma unroll
            for (int q = 0; q < 8; q++) a = fmaf(xs[ss][i + q], w[q], a);
            acc[ss] = a;
        }
    }
#pragma unroll
    for (int ss = 0; ss < 4; ss++) g_pre[d][b][st + ss][g] = acc[ss];
}

// ---------------- LSTM recurrence: 1 CTA/chain, pair-local gates, ONE sync/step -----
__global__ void __launch_bounds__(256, 1)
recur_k(int layer)
{
    __shared__ alignas(16) __half hbuf[2][HID];
    int t = threadIdx.x;
    int chain = blockIdx.x;
    int b = chain >> 1, d = chain & 1;
    int u = t >> 1, kh = t & 1;

    // weights: 4 gate rows x 32 half2 (my k-half), coalesced from g_WhhH
    __half2 wreg[4][32];
#pragma unroll
    for (int r = 0; r < 4; r++)
#pragma unroll
        for (int q = 0; q < 32; q++) wreg[r][q] = g_WhhH[layer][d][r][q][t];

    if (t < HID) hbuf[0][t] = __float2half(0.0f);
    __syncthreads();

    const float* __restrict__ preB = &g_pre[d][b][0][0];
    float* __restrict__ outB = &g_rnn[layer][b][0][0];
    float c = 0.0f;

    int s0 = d ? (SS - 1) : 0;
    float pre0 = __ldg(&preB[s0 * G4 + 0 * HID + u]);
    float pre1 = __ldg(&preB[s0 * G4 + 1 * HID + u]);
    float pre2 = __ldg(&preB[s0 * G4 + 2 * HID + u]);
    float pre3 = __ldg(&preB[s0 * G4 + 3 * HID + u]);

    for (int step = 0; step < SS; ++step) {
        int buf = step & 1, bn = buf ^ 1;
        int s = d ? (SS - 1 - step) : step;

        // matvec over my 64-k half: 4 rows x 32 HFMA2, 2 accumulators per row
        __half2 acc[4][2];
#pragma unroll
        for (int r = 0; r < 4; r++) { acc[r][0] = __float2half2_rn(0.0f); acc[r][1] = __float2half2_rn(0.0f); }
        const uint4* hp = reinterpret_cast<const uint4*>(&hbuf[buf][kh * 64]); // 8 x 16B
#pragma unroll
        for (int v = 0; v < 8; v++) {
            uint4 rr = hp[v];
            __half2 h0 = *reinterpret_cast<__half2*>(&rr.x);
            __half2 h1 = *reinterpret_cast<__half2*>(&rr.y);
            __half2 h2 = *reinterpret_cast<__half2*>(&rr.z);
            __half2 h3 = *reinterpret_cast<__half2*>(&rr.w);
#pragma unroll
            for (int r = 0; r < 4; r++) {
                acc[r][0] = __hfma2(wreg[r][4 * v + 0], h0, acc[r][0]);
                acc[r][1] = __hfma2(wreg[r][4 * v + 1], h1, acc[r][1]);
                acc[r][0] = __hfma2(wreg[r][4 * v + 2], h2, acc[r][0]);
                acc[r][1] = __hfma2(wreg[r][4 * v + 3], h3, acc[r][1]);
            }
        }
        float g[4];
#pragma unroll
        for (int r = 0; r < 4; r++) {
            float2 fa = __half22float2(acc[r][0]);
            float2 fb = __half22float2(acc[r][1]);
            g[r] = (fa.x + fa.y) + (fb.x + fb.y);
        }
        // combine k-halves within the pair (same warp, no barrier)
#pragma unroll
        for (int r = 0; r < 4; r++) g[r] += __shfl_xor_sync(0xffffffffu, g[r], 1);
        g[0] += pre0; g[1] += pre1; g[2] += pre2; g[3] += pre3;

        // prefetch next pre (independent of h chain)
        if (step + 1 < SS) {
            int sn = d ? (SS - 2 - step) : (step + 1);
            pre0 = __ldg(&preB[sn * G4 + 0 * HID + u]);
            pre1 = __ldg(&preB[sn * G4 + 1 * HID + u]);
            pre2 = __ldg(&preB[sn * G4 + 2 * HID + u]);
            pre3 = __ldg(&preB[sn * G4 + 3 * HID + u]);
        }

        // cell: both pair threads compute identically (deterministic), c in regs
        c = sig_ap(g[1]) * c + sig_ap(g[0]) * tanh_ap(g[2]);
        float h = sig_ap(g[3]) * tanh_ap(c);
        if (kh == 0) {
            hbuf[bn][u] = __float2half(h);
            outB[s * F2 + d * HID + u] = h;
        }
        __syncthreads();   // h publish — the only barrier per step
    }
}

// ---------------- post: fused cumsum + dterm/eterm + cls/bin MLPs --------------------
// grid (SS, BB), 128 threads. Block (0, b) additionally runs the full cumsum for
// batch b (overlaps with the other blocks' MLP work; completes before scores_k).
__global__ void post_k(const float* __restrict__ a_s0p, const float* __restrict__ bs1,
                       const float* __restrict__ ac0, const float* __restrict__ bc1,
                       const float* __restrict__ ac1, const float* __restrict__ wc2,
                       const float* __restrict__ bc2,
                       const float* __restrict__ ab0, const float* __restrict__ bb1,
                       const float* __restrict__ ab1, const float* __restrict__ wb2,
                       const float* __restrict__ bb2, float* __restrict__ out)
{
    int s = blockIdx.x, b = blockIdx.y, t = threadIdx.x; // 128
    __shared__ float pr[F2];
    __shared__ float h1[80];

    if (s == 0) {   // cumsum for this b: each thread walks 2 feature lanes
        float r0 = 0.0f, r1 = 0.0f;
        for (int ss = 0; ss < SS; ss++) {
            r0 += g_rnn[1][b][ss][t];
            r1 += g_rnn[1][b][ss][t + 128];
            g_cum[b][ss][t] = r0;
            g_cum[b][ss][t + 128] = r1;
        }
    }

    // dterm/eterm for (b, s)
    float a0 = *a_s0p;
    for (int p = t; p < F2; p += 128) pr[p] = preluf(g_rnn[1][b][s][p], a0);
    __syncthreads();
    {
        float ad = 0.0f, ae = 0.0f;
        for (int k = 0; k < F2; k++) {
            float p = pr[k];
            ad = fmaf(p, g_WdT[k][t], ad);
            ae = fmaf(p, g_WeT[k][t], ae);
        }
        g_dterm[b][s][t] = ad + ((t < 100) ? bs1[t] : 0.0f);
        g_eterm[b][s][t] = ae;
    }

    // CLS head (reuses pr: a_c0 prelu recomputed into pr)
    float a = *ac0;
    __syncthreads();
    for (int p = t; p < F2; p += 128) pr[p] = preluf(g_rnn[1][b][s][p], a);
    __syncthreads();
    if (t < 80) {
        float acc = bc1[t];
        for (int k = 0; k < F2; k++) acc = fmaf(pr[k], g_wc1T[k][t], acc);
        h1[t] = preluf(acc, *ac1);
    }
    __syncthreads();
    if (t < NCC) {
        float acc = bc2[t];
        for (int q = 0; q < 80; q++) acc = fmaf(h1[q], wc2[t * 80 + q], acc);
        out[(b * SS + s) * NCC + t] = acc;
    }
    __syncthreads();
    // BIN head
    a = *ab0;
    for (int p = t; p < F2; p += 128) pr[p] = preluf(g_rnn[1][b][s][p], a);
    __syncthreads();
    if (t < 80) {
        float acc = bb1[t];
        for (int k = 0; k < F2; k++) acc = fmaf(pr[k], g_wb1T[k][t], acc);
        h1[t] = preluf(acc, *ab1);
    }
    __syncthreads();
    if (t < 2) {
        float acc = bb2[t];
        for (int q = 0; q < 80; q++) acc = fmaf(h1[q], wb2[t * 80 + q], acc);
        out[20480 + (b * SS + s) * 2 + t] = acc;
    }
}

// ---------------- pairwise scores: f32x2 packed, block=(i,b), 256 threads ----------------
#define T2ROW 130
__global__ void __launch_bounds__(256) scores_k(const float* __restrict__ a_s0p,
                         const float* __restrict__ a_s1p,
                         const float* __restrict__ ws2, const float* __restrict__ bs2)
{
    extern __shared__ float smd[];
    float* cum_i = smd;                                  // 256 floats
    u64* T2 = reinterpret_cast<u64*>(smd + 256);         // [64][T2ROW]
    int i = blockIdx.x, b = blockIdx.y, tid = threadIdx.x;
    int oq = tid & 15, jg = tid >> 4;   // 16 output-groups x 16 j-groups (4 j each)
    float a0 = *a_s0p, a1 = *a_s1p;
    for (int p = tid; p < F2; p += 256) cum_i[p] = g_cum[b][i][p];
    float dt[8], w2v[8];
#pragma unroll
    for (int r = 0; r < 8; r++) {
        int o = oq * 8 + r;
        dt[r] = g_dterm[b][i][o];
        w2v[r] = (o < 100) ? ws2[o] : 0.0f;
    }
    float bs2v = bs2[0];
    __syncthreads();
    const ulonglong2* __restrict__ W2 = reinterpret_cast<const ulonglong2*>(&g_WcT[0][0]);
    for (int tile = 0; tile < 4; tile++) {
        int j0 = tile * 64;
        u64 acc[4][4];
#pragma unroll
        for (int r4 = 0; r4 < 4; r4++)
#pragma unroll
            for (int p2 = 0; p2 < 4; p2++) acc[r4][p2] = 0ull;

        for (int kh = 0; kh < 2; kh++) {
            int kb = kh * 128;
            for (int p = tid; p < 64 * 128; p += 256) {
                int lj = p >> 7, k = p & 127;
                float v = preluf(g_cum[b][j0 + lj][kb + k] - cum_i[kb + k], a0);
                T2[lj * T2ROW + k] = packf2(v, v);
            }
            __syncthreads();
            const u64* Ta = &T2[(jg * 4 + 0) * T2ROW];
            const u64* Tb = &T2[(jg * 4 + 1) * T2ROW];
            const u64* Tc = &T2[(jg * 4 + 2) * T2ROW];
            const u64* Td = &T2[(jg * 4 + 3) * T2ROW];
#pragma unroll 2
            for (int k = 0; k < 128; k++) {
                ulonglong2 wA = W2[(kb + k) * 32 + 2 * oq];
                ulonglong2 wB = W2[(kb + k) * 32 + 2 * oq + 1];
                u64 t0 = Ta[k], t1 = Tb[k], t2 = Tc[k], t3 = Td[k];
                fma2(acc[0][0], t0, wA.x); fma2(acc[0][1], t0, wA.y);
                fma2(acc[0][2], t0, wB.x); fma2(acc[0][3], t0, wB.y);
                fma2(acc[1][0], t1, wA.x); fma2(acc[1][1], t1, wA.y);
                fma2(acc[1][2], t1, wB.x); fma2(acc[1][3], t1, wB.y);
                fma2(acc[2][0], t2, wA.x); fma2(acc[2][1], t2, wA.y);
                fma2(acc[2][2], t2, wB.x); fma2(acc[2][3], t2, wB.y);
                fma2(acc[3][0], t3, wA.x); fma2(acc[3][1], t3, wA.y);
                fma2(acc[3][2], t3, wB.x); fma2(acc[3][3], t3, wB.y);
            }
            __syncthreads();
        }
#pragma unroll
        for (int r4 = 0; r4 < 4; r4++) {
            int j = j0 + jg * 4 + r4;
            float part = 0.0f;
#pragma unroll
            for (int p2 = 0; p2 < 4; p2++) {
                float2 f = unpackf2(acc[r4][p2]);
                int r = 2 * p2, o = oq * 8 + r;
                float h0 = f.x + dt[r]     + g_eterm[b][j][o];
                float h1 = f.y + dt[r + 1] + g_eterm[b][j][o + 1];
                part = fmaf(preluf(h0, a1), w2v[r],     part);
                part = fmaf(preluf(h1, a1), w2v[r + 1], part);
            }
#pragma unroll
            for (int off = 8; off > 0; off >>= 1)
                part += __shfl_down_sync(0xffffffffu, part, off, 16);
            if (oq == 0) g_scoresT[b][j][i] = part + bs2v;
        }
    }
}

// ---------------- DP backpointers + fused backtrack ----------------
__global__ void dp_k(const int* __restrict__ lengths, float* __restrict__ out)
{
    int b = blockIdx.x, t = threadIdx.x; // 64 threads
    __shared__ float best[SS];
    __shared__ int bptr[SS];
    __shared__ float rv[2];
    __shared__ int ri[2];
    for (int p = t; p < SS; p += 64) { best[p] = 0.0f; out[21504 + b * SS + p] = 0.0f; }
    if (t == 0) bptr[0] = 0;
    __syncthreads();
    float sc_next = g_scoresT[b][1][t];   // i=1: start=0
    for (int i = 1; i < SS; i++) {
        int start = (i > WSEG) ? (i - WSEG) : 0;
        float sc = sc_next;
        if (i + 1 < SS) {
            int st2 = (i + 1 > WSEG) ? (i + 1 - WSEG) : 0;
            sc_next = g_scoresT[b][i + 1][st2 + t];
        }
        int j = start + t;
        float v = (j < i) ? best[j] + sc : -1000000000.0f;
        int idx = j;
#pragma unroll
        for (int off = 16; off > 0; off >>= 1) {
            float ov = __shfl_down_sync(0xffffffffu, v, off);
            int oi = __shfl_down_sync(0xffffffffu, idx, off);
            if (ov > v || (ov == v && oi < idx)) { v = ov; idx = oi; }
        }
        if ((t & 31) == 0) { rv[t >> 5] = v; ri[t >> 5] = idx; }
        __syncthreads();
        if (t == 0) {
            float v0 = rv[0], v1 = rv[1];
            int i0 = ri[0], i1 = ri[1];
            if (v1 > v0 || (v1 == v0 && i1 < i0)) { v0 = v1; i0 = i1; }
            best[i] = v0;
            bptr[i] = i0;
        }
        __syncthreads();
    }
    // fused backtrack: pred_scores = best[len-1]; bmask via smem pointer chase
    if (t == 0) {
        int cur = lengths[b] - 1;
        out[22016 + b] = (cur > 0) ? best[cur] : 0.0f;
        for (int it = 0; it < SS; it++) {
            out[21504 + b * SS + cur] = 1.0f;
            if (cur > 0) cur = bptr[cur];
        }
    }
}

// ---------------- launch ----------------
extern "C" void kernel_launch(void* const* d_in, const int* in_sizes, int n_in,
                              void* d_out, int out_size)
{
    const float* x       = (const float*)d_in[0];
    const int*   lengths = (const int*)d_in[1];
    const float* wih0f = (const float*)d_in[2];
    const float* whh0f = (const float*)d_in[3];
    const float* bl0f  = (const float*)d_in[4];
    const float* wih0b = (const float*)d_in[5];
    const float* whh0b = (const float*)d_in[6];
    const float* bl0b  = (const float*)d_in[7];
    const float* wih1f = (const float*)d_in[8];
    const float* whh1f = (const float*)d_in[9];
    const float* bl1f  = (const float*)d_in[10];
    const float* wih1b = (const float*)d_in[11];
    const float* whh1b = (const float*)d_in[12];
    const float* bl1b  = (const float*)d_in[13];
    const float* a_s0 = (const float*)d_in[14];
    const float* w_s1 = (const float*)d_in[15];
    const float* b_s1 = (const float*)d_in[16];
    const float* a_s1 = (const float*)d_in[17];
    const float* w_s2 = (const float*)d_in[18];
    const float* b_s2 = (const float*)d_in[19];
    const float* a_c0 = (const float*)d_in[20];
    const float* w_c1 = (const float*)d_in[21];
    const float* b_c1 = (const float*)d_in[22];
    const float* a_c1 = (const float*)d_in[23];
    const float* w_c2 = (const float*)d_in[24];
    const float* b_c2 = (const float*)d_in[25];
    const float* a_b0 = (const float*)d_in[26];
    const float* w_b1 = (const float*)d_in[27];
    const float* b_b1 = (const float*)d_in[28];
    const float* a_b1 = (const float*)d_in[29];
    const float* w_b2 = (const float*)d_in[30];
    const float* b_b2 = (const float*)d_in[31];
    float* out = (float*)d_out;

    const int SCORES_SMEM = 256 * 4 + 64 * T2ROW * 8;   // ~67.6 KB
    cudaFuncSetAttribute(scores_k, cudaFuncAttributeMaxDynamicSharedMemorySize, SCORES_SMEM);

    prep_k<<<512, 256>>>(wih0f, wih0b, wih1f, wih1b,
                         whh0f, whh0b, whh1f, whh1b, w_s1, w_c1, w_b1);
    dummy_k<<<1, 32>>>();   // index shim: puts recur_k in the profiler's capture slot

    inproj_k<INP><<<dim3(SS / 4, BB, 2), 512>>>(x, bl0f, bl0b, 0);
    recur_k<<<4, 256>>>(0);
    inproj_k<F2><<<dim3(SS / 4, BB, 2), 512>>>(x, bl1f, bl1b, 1);
    recur_k<<<4, 256>>>(1);

    post_k<<<dim3(SS, BB), 128>>>(a_s0, b_s1,
                                  a_c0, b_c1, a_c1, w_c2, b_c2,
                                  a_b0, b_b1, a_b1, w_b2, b_b2, out);
    scores_k<<<dim3(SS, BB), 256, SCORES_SMEM>>>(a_s0, a_s1, w_s2, b_s2);
    dp_k<<<BB, 64>>>(lengths, out);
}

// round 17
// speedup vs baseline: 2.1288x; 1.1258x over previous
#include <cuda_runtime.h>
#include <cuda_fp16.h>
#include <math.h>
#include <stdint.h>

// Problem constants
#define BB   2
#define SS   256
#define INP  80
#define HID  128
#define F2   256
#define G4   512   // 4*HID
#define NCC  40
#define WSEG 64

typedef unsigned long long u64;

// ---------------- device scratch (no allocation allowed) ----------------
__device__ float g_WihT0[2][INP][G4];    // [dir][i][g]
__device__ float g_WihT1[2][F2][G4];
__device__ __half2 g_WhhH[2][2][4][32][256]; // [layer][dir][gate r][q][thread t] fp16 pairs
__device__ float g_pre[2][BB][SS][G4];   // [dir][b][s][g]  (reused per layer)
__device__ float g_rnn[2][BB][SS][F2];   // [layer][b][s][f]
__device__ float g_cum[BB][SS][F2];
__device__ float g_WcT[F2][128];         // w_s1 c-part transposed, o padded 100->128 (zeros)
__device__ float g_WdT[F2][128];
__device__ float g_WeT[F2][128];
__device__ float g_wc1T[F2][80];
__device__ float g_wb1T[F2][80];
__device__ float g_dterm[BB][SS][128];   // prelu(rnn_i)@Wd^T + b_s1 (padded)
__device__ float g_eterm[BB][SS][128];   // prelu(rnn_j)@We^T
__device__ float g_scoresT[BB][SS][SS];  // scoresT[b][j][i] = scores[i][j] (DP reads rows)

__device__ __forceinline__ float preluf(float x, float a) { return x >= 0.0f ? x : a * x; }
// single-MUFU activations (tanh.approx.f32)
__device__ __forceinline__ float tanh_ap(float x) {
    float y; asm("tanh.approx.f32 %0, %1;" : "=f"(y) : "f"(x)); return y;
}
__device__ __forceinline__ float sig_ap(float x) { return fmaf(tanh_ap(0.5f * x), 0.5f, 0.5f); }

// ---------------- f32x2 packed math helpers ----------------
__device__ __forceinline__ void fma2(u64& acc, u64 a, u64 b) {
    asm("fma.rn.f32x2 %0, %1, %2, %0;" : "+l"(acc) : "l"(a), "l"(b));
}
__device__ __forceinline__ u64 packf2(float lo, float hi) {
    u64 r; asm("mov.b64 %0, {%1, %2};" : "=l"(r) : "f"(lo), "f"(hi)); return r;
}
__device__ __forceinline__ float2 unpackf2(u64 v) {
    float2 r; asm("mov.b64 {%0, %1}, %2;" : "=f"(r.x), "=f"(r.y) : "l"(v)); return r;
}

// ---------------- dummy: shifts launch indices so ncu's capture slot lands on recur_k
__global__ void dummy_k() {}

// ---------------- prep: transpose weights into friendly layouts ----------------
__global__ void prep_k(const float* __restrict__ wih0f,
                       const float* __restrict__ wih0b,
                       const float* __restrict__ wih1f,
                       const float* __restrict__ wih1b,
                       const float* __restrict__ whh0f,
                       const float* __restrict__ whh0b,
                       const float* __restrict__ whh1f,
                       const float* __restrict__ whh1b,
                       const float* __restrict__ ws1,  const float* __restrict__ wc1,
                       const float* __restrict__ wb1)
{
    int idx = blockIdx.x * blockDim.x + threadIdx.x;
    int n = gridDim.x * blockDim.x;
    for (int p = idx; p < 2 * INP * G4; p += n) {
        int d = p / (INP * G4), r = p % (INP * G4), i = r / G4, g = r % G4;
        g_WihT0[d][i][g] = (d ? wih0b : wih0f)[g * INP + i];
    }
    for (int p = idx; p < 2 * F2 * G4; p += n) {
        int d = p / (F2 * G4), r = p % (F2 * G4), i = r / G4, g = r % G4;
        g_WihT1[d][i][g] = (d ? wih1b : wih1f)[g * F2 + i];
    }
    // recurrence weights, fp16, register-layout order: [l][d][r][q][t]
    for (int p = idx; p < 2 * 2 * 4 * 32 * 256; p += n) {
        int l = p / (2 * 4 * 32 * 256), r1 = p % (2 * 4 * 32 * 256);
        int d = r1 / (4 * 32 * 256),    r2 = r1 % (4 * 32 * 256);
        int r = r2 / (32 * 256),        r3 = r2 % (32 * 256);
        int q = r3 / 256, t = r3 % 256;
        int u = t >> 1, kh = t & 1;
        const float* w = l ? (d ? whh1b : whh1f) : (d ? whh0b : whh0f);
        int row = r * 128 + u, k = kh * 64 + 2 * q;
        g_WhhH[l][d][r][q][t] = __floats2half2_rn(w[row * 128 + k], w[row * 128 + k + 1]);
    }
    for (int p = idx; p < F2 * 128; p += n) {
        int k = p / 128, o = p % 128;
        g_WcT[k][o] = (o < 100) ? ws1[o * 768 + k]        : 0.0f;
        g_WdT[k][o] = (o < 100) ? ws1[o * 768 + 256 + k]  : 0.0f;
        g_WeT[k][o] = (o < 100) ? ws1[o * 768 + 512 + k]  : 0.0f;
    }
    for (int p = idx; p < F2 * 80; p += n) {
        int k = p / 80, o = p % 80;
        g_wc1T[k][o] = wc1[o * F2 + k];
        g_wb1T[k][o] = wb1[o * F2 + k];
    }
}

// ---------------- input projection: pre = x @ Wih^T + b ----------------
template <int INDIM>
__global__ void inproj_k(const float* __restrict__ x0,
                         const float* __restrict__ bias_f, const float* __restrict__ bias_b,
                         int layer)
{
    int st = blockIdx.x * 4, b = blockIdx.y, d = blockIdx.z, g = threadIdx.x;
    __shared__ float xs[4][INDIM];
    const float* xin = layer ? &g_rnn[0][0][0][0] : x0;
    for (int p = g; p < 4 * INDIM; p += 512) {
        int ss = p / INDIM, i = p % INDIM;
        xs[ss][i] = xin[(b * SS + st + ss) * INDIM + i];
    }
    __syncthreads();
    const float* W = (INDIM == INP) ? &g_WihT0[d][0][0] : &g_WihT1[d][0][0];
    float bg = (d ? bias_b : bias_f)[g];
    float acc[4] = {bg, bg, bg, bg};
    for (int i = 0; i < INDIM; i += 8) {
        float w[8];
#pragma unroll
        for (int q = 0; q < 8; q++) w[q] = W[(i + q) * G4 + g];
#pragma unroll
        for (int ss = 0; ss < 4; ss++) {
            float a = acc[ss];
#pragma unroll
            for (int q = 0; q < 8; q++) a = fmaf(xs[ss][i + q], w[q], a);
            acc[ss] = a;
        }
    }
#pragma unroll
    for (int ss = 0; ss < 4; ss++) g_pre[d][b][st + ss][g] = acc[ss];
}

// ---------------- LSTM recurrence: 1 CTA/chain, pair-local gates, ONE sync/step -----
__global__ void __launch_bounds__(256, 1)
recur_k(int layer)
{
    __shared__ alignas(16) __half hbuf[2][HID];
    int t = threadIdx.x;
    int chain = blockIdx.x;
    int b = chain >> 1, d = chain & 1;
    int u = t >> 1, kh = t & 1;

    __half2 wreg[4][32];
#pragma unroll
    for (int r = 0; r < 4; r++)
#pragma unroll
        for (int q = 0; q < 32; q++) wreg[r][q] = g_WhhH[layer][d][r][q][t];

    if (t < HID) hbuf[0][t] = __float2half(0.0f);
    __syncthreads();

    const float* __restrict__ preB = &g_pre[d][b][0][0];
    float* __restrict__ outB = &g_rnn[layer][b][0][0];
    float c = 0.0f;

    int s0 = d ? (SS - 1) : 0;
    float pre0 = __ldg(&preB[s0 * G4 + 0 * HID + u]);
    float pre1 = __ldg(&preB[s0 * G4 + 1 * HID + u]);
    float pre2 = __ldg(&preB[s0 * G4 + 2 * HID + u]);
    float pre3 = __ldg(&preB[s0 * G4 + 3 * HID + u]);

    for (int step = 0; step < SS; ++step) {
        int buf = step & 1, bn = buf ^ 1;
        int s = d ? (SS - 1 - step) : step;

        __half2 acc[4][2];
#pragma unroll
        for (int r = 0; r < 4; r++) { acc[r][0] = __float2half2_rn(0.0f); acc[r][1] = __float2half2_rn(0.0f); }
        const uint4* hp = reinterpret_cast<const uint4*>(&hbuf[buf][kh * 64]); // 8 x 16B
#pragma unroll
        for (int v = 0; v < 8; v++) {
            uint4 rr = hp[v];
            __half2 h0 = *reinterpret_cast<__half2*>(&rr.x);
            __half2 h1 = *reinterpret_cast<__half2*>(&rr.y);
            __half2 h2 = *reinterpret_cast<__half2*>(&rr.z);
            __half2 h3 = *reinterpret_cast<__half2*>(&rr.w);
#pragma unroll
            for (int r = 0; r < 4; r++) {
                acc[r][0] = __hfma2(wreg[r][4 * v + 0], h0, acc[r][0]);
                acc[r][1] = __hfma2(wreg[r][4 * v + 1], h1, acc[r][1]);
                acc[r][0] = __hfma2(wreg[r][4 * v + 2], h2, acc[r][0]);
                acc[r][1] = __hfma2(wreg[r][4 * v + 3], h3, acc[r][1]);
            }
        }
        float g[4];
#pragma unroll
        for (int r = 0; r < 4; r++) {
            float2 fa = __half22float2(acc[r][0]);
            float2 fb = __half22float2(acc[r][1]);
            g[r] = (fa.x + fa.y) + (fb.x + fb.y);
        }
#pragma unroll
        for (int r = 0; r < 4; r++) g[r] += __shfl_xor_sync(0xffffffffu, g[r], 1);
        g[0] += pre0; g[1] += pre1; g[2] += pre2; g[3] += pre3;

        if (step + 1 < SS) {
            int sn = d ? (SS - 2 - step) : (step + 1);
            pre0 = __ldg(&preB[sn * G4 + 0 * HID + u]);
            pre1 = __ldg(&preB[sn * G4 + 1 * HID + u]);
            pre2 = __ldg(&preB[sn * G4 + 2 * HID + u]);
            pre3 = __ldg(&preB[sn * G4 + 3 * HID + u]);
        }

        c = sig_ap(g[1]) * c + sig_ap(g[0]) * tanh_ap(g[2]);
        float h = sig_ap(g[3]) * tanh_ap(c);
        if (kh == 0) {
            hbuf[bn][u] = __float2half(h);
            outB[s * F2 + d * HID + u] = h;
        }
        __syncthreads();
    }
}

// ---------------- post: fused cumsum + dterm/eterm + cls/bin MLPs --------------------
__global__ void post_k(const float* __restrict__ a_s0p, const float* __restrict__ bs1,
                       const float* __restrict__ ac0, const float* __restrict__ bc1,
                       const float* __restrict__ ac1, const float* __restrict__ wc2,
                       const float* __restrict__ bc2,
                       const float* __restrict__ ab0, const float* __restrict__ bb1,
                       const float* __restrict__ ab1, const float* __restrict__ wb2,
                       const float* __restrict__ bb2, float* __restrict__ out)
{
    int s = blockIdx.x, b = blockIdx.y, t = threadIdx.x; // 128
    __shared__ float pr[F2];
    __shared__ float h1[80];

    if (s == 0) {   // cumsum for this b
        float r0 = 0.0f, r1 = 0.0f;
        for (int ss = 0; ss < SS; ss++) {
            r0 += g_rnn[1][b][ss][t];
            r1 += g_rnn[1][b][ss][t + 128];
            g_cum[b][ss][t] = r0;
            g_cum[b][ss][t + 128] = r1;
        }
    }

    float a0 = *a_s0p;
    for (int p = t; p < F2; p += 128) pr[p] = preluf(g_rnn[1][b][s][p], a0);
    __syncthreads();
    {
        float ad = 0.0f, ae = 0.0f;
        for (int k = 0; k < F2; k++) {
            float p = pr[k];
            ad = fmaf(p, g_WdT[k][t], ad);
            ae = fmaf(p, g_WeT[k][t], ae);
        }
        g_dterm[b][s][t] = ad + ((t < 100) ? bs1[t] : 0.0f);
        g_eterm[b][s][t] = ae;
    }

    float a = *ac0;
    __syncthreads();
    for (int p = t; p < F2; p += 128) pr[p] = preluf(g_rnn[1][b][s][p], a);
    __syncthreads();
    if (t < 80) {
        float acc = bc1[t];
        for (int k = 0; k < F2; k++) acc = fmaf(pr[k], g_wc1T[k][t], acc);
        h1[t] = preluf(acc, *ac1);
    }
    __syncthreads();
    if (t < NCC) {
        float acc = bc2[t];
        for (int q = 0; q < 80; q++) acc = fmaf(h1[q], wc2[t * 80 + q], acc);
        out[(b * SS + s) * NCC + t] = acc;
    }
    __syncthreads();
    a = *ab0;
    for (int p = t; p < F2; p += 128) pr[p] = preluf(g_rnn[1][b][s][p], a);
    __syncthreads();
    if (t < 80) {
        float acc = bb1[t];
        for (int k = 0; k < F2; k++) acc = fmaf(pr[k], g_wb1T[k][t], acc);
        h1[t] = preluf(acc, *ab1);
    }
    __syncthreads();
    if (t < 2) {
        float acc = bb2[t];
        for (int q = 0; q < 80; q++) acc = fmaf(h1[q], wb2[t * 80 + q], acc);
        out[20480 + (b * SS + s) * 2 + t] = acc;
    }
}

// ---------------- pairwise scores v3: grid (SS, 2, BB), 16j x 4o per thread ----------
// CTA = (i, j-half, b): 128 j. Thread: oq = tid&31 -> o = oq*4..+3; jg = tid>>5 ->
// rows jg*16..+15. acc[16][2] u64. k in 4 quarters of 64 via T2[128][T2R] u64 smem
// (value duplicated in both f32x2 lanes). One 16B W load per k feeds 32 fma2.
#define T2R 66
__global__ void __launch_bounds__(256) scores_k(const float* __restrict__ a_s0p,
                         const float* __restrict__ a_s1p,
                         const float* __restrict__ ws2, const float* __restrict__ bs2)
{
    extern __shared__ float smd[];
    float* cum_i = smd;                                  // 256 floats
    u64* T2 = reinterpret_cast<u64*>(smd + 256);         // [128][T2R]
    int i = blockIdx.x, jh = blockIdx.y, b = blockIdx.z, tid = threadIdx.x;
    int oq = tid & 31, jg = tid >> 5;    // o = oq*4..+3 ; rows jg*16..+15
    int jbase = jh * 128;
    float a0 = *a_s0p, a1 = *a_s1p;
    cum_i[tid] = g_cum[b][i][tid];
    float4 dt4 = *reinterpret_cast<const float4*>(&g_dterm[b][i][oq * 4]);
    float dt[4] = {dt4.x, dt4.y, dt4.z, dt4.w};
    float w2v[4];
#pragma unroll
    for (int r = 0; r < 4; r++) {
        int o = oq * 4 + r;
        w2v[r] = (o < 100) ? ws2[o] : 0.0f;
    }
    float bs2v = bs2[0];
    __syncthreads();

    const ulonglong2* __restrict__ W2 = reinterpret_cast<const ulonglong2*>(&g_WcT[0][0]);
    u64 acc[16][2];
#pragma unroll
    for (int jj = 0; jj < 16; jj++) { acc[jj][0] = 0ull; acc[jj][1] = 0ull; }

    for (int kq = 0; kq < 4; kq++) {
        int kb = kq * 64;
        // fill T2[128][64] for this k-quarter
        for (int p = tid; p < 128 * 64; p += 256) {
            int lj = p >> 6, k = p & 63;
            float v = preluf(g_cum[b][jbase + lj][kb + k] - cum_i[kb + k], a0);
            T2[lj * T2R + k] = packf2(v, v);
        }
        __syncthreads();
        const u64* Tbase = &T2[(jg * 16) * T2R];
#pragma unroll 2
        for (int k = 0; k < 64; k++) {
            ulonglong2 w = W2[(kb + k) * 32 + oq];   // 16B = 4 outputs
#pragma unroll
            for (int jj = 0; jj < 16; jj++) {
                u64 tv = Tbase[jj * T2R + k];
                fma2(acc[jj][0], tv, w.x);
                fma2(acc[jj][1], tv, w.y);
            }
        }
        __syncthreads();
    }

    // epilogue: 16 j per thread, 4 o each, full-warp reduction over o
#pragma unroll
    for (int jj = 0; jj < 16; jj++) {
        int j = jbase + jg * 16 + jj;
        float4 et = *reinterpret_cast<const float4*>(&g_eterm[b][j][oq * 4]);
        float2 f0 = unpackf2(acc[jj][0]);
        float2 f1 = unpackf2(acc[jj][1]);
        float part = preluf(f0.x + dt[0] + et.x, a1) * w2v[0];
        part = fmaf(preluf(f0.y + dt[1] + et.y, a1), w2v[1], part);
        part = fmaf(preluf(f1.x + dt[2] + et.z, a1), w2v[2], part);
        part = fmaf(preluf(f1.y + dt[3] + et.w, a1), w2v[3], part);
#pragma unroll
        for (int off = 16; off > 0; off >>= 1)
            part += __shfl_down_sync(0xffffffffu, part, off);
        if (oq == 0) g_scoresT[b][j][i] = part + bs2v;
    }
}

// ---------------- DP backpointers + fused backtrack: single warp, no block barriers --
__global__ void dp_k(const int* __restrict__ lengths, float* __restrict__ out)
{
    int b = blockIdx.x, lane = threadIdx.x; // 32 threads
    __shared__ float best[SS];
    __shared__ int bptr[SS];
    for (int p = lane; p < SS; p += 32) { best[p] = 0.0f; out[21504 + b * SS + p] = 0.0f; }
    if (lane == 0) bptr[0] = 0;
    __syncwarp();
    for (int i = 1; i < SS; i++) {
        int start = (i > WSEG) ? (i - WSEG) : 0;
        int j1 = start + lane, j2 = start + 32 + lane;
        float sc1 = g_scoresT[b][i][j1];
        float sc2 = g_scoresT[b][i][j2];
        float v = (j1 < i) ? best[j1] + sc1 : -1000000000.0f;
        int idx = j1;
        float v2 = (j2 < i) ? best[j2] + sc2 : -1000000000.0f;
        if (v2 > v) { v = v2; idx = j2; }   // j2 > j1: tie keeps smaller index
#pragma unroll
        for (int off = 16; off > 0; off >>= 1) {
            float ov = __shfl_down_sync(0xffffffffu, v, off);
            int oi = __shfl_down_sync(0xffffffffu, idx, off);
            if (ov > v || (ov == v && oi < idx)) { v = ov; idx = oi; }
        }
        if (lane == 0) { best[i] = v; bptr[i] = idx; }
        __syncwarp();
    }
    // fused backtrack: pred_scores = best[len-1]; bmask via smem pointer chase
    if (lane == 0) {
        int cur = lengths[b] - 1;
        out[22016 + b] = (cur > 0) ? best[cur] : 0.0f;
        for (int it = 0; it < SS; it++) {
            out[21504 + b * SS + cur] = 1.0f;
            if (cur > 0) cur = bptr[cur];
        }
    }
}

// ---------------- launch ----------------
extern "C" void kernel_launch(void* const* d_in, const int* in_sizes, int n_in,
                              void* d_out, int out_size)
{
    const float* x       = (const float*)d_in[0];
    const int*   lengths = (const int*)d_in[1];
    const float* wih0f = (const float*)d_in[2];
    const float* whh0f = (const float*)d_in[3];
    const float* bl0f  = (const float*)d_in[4];
    const float* wih0b = (const float*)d_in[5];
    const float* whh0b = (const float*)d_in[6];
    const float* bl0b  = (const float*)d_in[7];
    const float* wih1f = (const float*)d_in[8];
    const float* whh1f = (const float*)d_in[9];
    const float* bl1f  = (const float*)d_in[10];
    const float* wih1b = (const float*)d_in[11];
    const float* whh1b = (const float*)d_in[12];
    const float* bl1b  = (const float*)d_in[13];
    const float* a_s0 = (const float*)d_in[14];
    const float* w_s1 = (const float*)d_in[15];
    const float* b_s1 = (const float*)d_in[16];
    const float* a_s1 = (const float*)d_in[17];
    const float* w_s2 = (const float*)d_in[18];
    const float* b_s2 = (const float*)d_in[19];
    const float* a_c0 = (const float*)d_in[20];
    const float* w_c1 = (const float*)d_in[21];
    const float* b_c1 = (const float*)d_in[22];
    const float* a_c1 = (const float*)d_in[23];
    const float* w_c2 = (const float*)d_in[24];
    const float* b_c2 = (const float*)d_in[25];
    const float* a_b0 = (const float*)d_in[26];
    const float* w_b1 = (const float*)d_in[27];
    const float* b_b1 = (const float*)d_in[28];
    const float* a_b1 = (const float*)d_in[29];
    const float* w_b2 = (const float*)d_in[30];
    const float* b_b2 = (const float*)d_in[31];
    float* out = (float*)d_out;

    const int SCORES_SMEM = 256 * 4 + 128 * T2R * 8;   // ~68.6 KB
    cudaFuncSetAttribute(scores_k, cudaFuncAttributeMaxDynamicSharedMemorySize, SCORES_SMEM);

    prep_k<<<512, 256>>>(wih0f, wih0b, wih1f, wih1b,
                         whh0f, whh0b, whh1f, whh1b, w_s1, w_c1, w_b1);
    dummy_k<<<1, 32>>>();   // index shim: keeps recur_k in the profiler's capture slot

    inproj_k<INP><<<dim3(SS / 4, BB, 2), 512>>>(x, bl0f, bl0b, 0);
    recur_k<<<4, 256>>>(0);
    inproj_k<F2><<<dim3(SS / 4, BB, 2), 512>>>(x, bl1f, bl1b, 1);
    recur_k<<<4, 256>>>(1);

    post_k<<<dim3(SS, BB), 128>>>(a_s0, b_s1,
                                  a_c0, b_c1, a_c1, w_c2, b_c2,
                                  a_b0, b_b1, a_b1, w_b2, b_b2, out);
    scores_k<<<dim3(SS, 2, BB), 256, SCORES_SMEM>>>(a_s0, a_s1, w_s2, b_s2);
    dp_k<<<BB, 32>>>(lengths, out);
}